// round 1
// baseline (speedup 1.0000x reference)
#include <cuda_runtime.h>
#include <cuda_bf16.h>
#include <cstdint>

// ---------------------------------------------------------------------------
// GroupedQueryAttention baseline (fp32, FFMA)
//   x[2048,2048] @ wq -> Q[2048,2048]
//   x @ wk -> K[2048,512], x @ wv -> V[2048,512]
//   RoPE(Q), RoPE(K)
//   flash-style attention (32 heads, kv-head = h/4, head_dim 64, full softmax)
//   attn_out[2048,2048] @ wo -> out
// ---------------------------------------------------------------------------

#define SEQ      2048
#define DIM      2048
#define KVDIM    512
#define NHEADS   32
#define NKV      8
#define GROUP    4
#define HDIM     64

// Scratch (allocation-free rule: __device__ globals)
__device__ float g_Q[SEQ * DIM];
__device__ float g_K[SEQ * KVDIM];
__device__ float g_V[SEQ * KVDIM];
__device__ float g_O[SEQ * DIM];

// ---------------------------------------------------------------------------
// Tiled SGEMM: C[M,N] = A[M,K] * B[K,N], all row-major, dims multiple of tile
// ---------------------------------------------------------------------------
#define BM 128
#define BN 128
#define BKK 16
#define TM 8
#define TN 8

__global__ void __launch_bounds__(256) sgemm_kernel(
    const float* __restrict__ A, const float* __restrict__ B,
    float* __restrict__ C, int M, int N, int K)
{
    __shared__ __align__(16) float As[BKK][BM];
    __shared__ __align__(16) float Bs[BKK][BN];

    const int tid  = threadIdx.x;
    const int row0 = blockIdx.y * BM;
    const int col0 = blockIdx.x * BN;
    const int tx   = tid % (BN / TN);   // 0..15
    const int ty   = tid / (BN / TN);   // 0..15

    float acc[TM][TN];
    #pragma unroll
    for (int i = 0; i < TM; i++)
        #pragma unroll
        for (int j = 0; j < TN; j++) acc[i][j] = 0.f;

    for (int k0 = 0; k0 < K; k0 += BKK) {
        // Load A tile (BM x BKK) as float4 along K, store transposed
        #pragma unroll
        for (int i = tid; i < BM * BKK / 4; i += 256) {
            int m  = i / (BKK / 4);
            int kc = (i % (BKK / 4)) * 4;
            float4 v = *reinterpret_cast<const float4*>(
                &A[(size_t)(row0 + m) * K + k0 + kc]);
            As[kc + 0][m] = v.x;
            As[kc + 1][m] = v.y;
            As[kc + 2][m] = v.z;
            As[kc + 3][m] = v.w;
        }
        // Load B tile (BKK x BN) as float4 along N
        #pragma unroll
        for (int i = tid; i < BKK * BN / 4; i += 256) {
            int k  = i / (BN / 4);
            int nc = (i % (BN / 4)) * 4;
            *reinterpret_cast<float4*>(&Bs[k][nc]) =
                *reinterpret_cast<const float4*>(
                    &B[(size_t)(k0 + k) * N + col0 + nc]);
        }
        __syncthreads();

        #pragma unroll
        for (int k = 0; k < BKK; k++) {
            float ra[TM], rb[TN];
            #pragma unroll
            for (int i = 0; i < TM; i += 4) {
                float4 v = *reinterpret_cast<const float4*>(&As[k][ty * TM + i]);
                ra[i] = v.x; ra[i+1] = v.y; ra[i+2] = v.z; ra[i+3] = v.w;
            }
            #pragma unroll
            for (int j = 0; j < TN; j += 4) {
                float4 v = *reinterpret_cast<const float4*>(&Bs[k][tx * TN + j]);
                rb[j] = v.x; rb[j+1] = v.y; rb[j+2] = v.z; rb[j+3] = v.w;
            }
            #pragma unroll
            for (int i = 0; i < TM; i++)
                #pragma unroll
                for (int j = 0; j < TN; j++)
                    acc[i][j] += ra[i] * rb[j];
        }
        __syncthreads();
    }

    #pragma unroll
    for (int i = 0; i < TM; i++) {
        #pragma unroll
        for (int j = 0; j < TN; j += 4) {
            float4 v = make_float4(acc[i][j], acc[i][j+1], acc[i][j+2], acc[i][j+3]);
            *reinterpret_cast<float4*>(
                &C[(size_t)(row0 + ty * TM + i) * N + col0 + tx * TN + j]) = v;
        }
    }
}

// ---------------------------------------------------------------------------
// RoPE in-place: buf[s, h*64 + d], grid.x = s, blockDim = n_heads*32
// ---------------------------------------------------------------------------
__global__ void rope_kernel(float* __restrict__ buf, int stride)
{
    int s = blockIdx.x;
    int h = threadIdx.x >> 5;
    int d = threadIdx.x & 31;
    // inv_freq = 10000^{-d/32}
    float inv = expf(-(float)d * (logf(10000.0f) / 32.0f));
    float ang = (float)s * inv;
    float c, sn;
    sincosf(ang, &sn, &c);
    float* p = buf + (size_t)s * stride + h * HDIM;
    float x1 = p[d];
    float x2 = p[d + 32];
    p[d]      = x1 * c - x2 * sn;
    p[d + 32] = x2 * c + x1 * sn;
}

// ---------------------------------------------------------------------------
// Flash-style attention. grid = (SEQ/128, NHEADS), 128 threads.
// Thread t owns query q = blockIdx.x*128 + t; q-vector + accumulator in regs.
// ---------------------------------------------------------------------------
#define AK 16   // keys per tile

__global__ void __launch_bounds__(128) attn_kernel(
    const float* __restrict__ Q, const float* __restrict__ Kg,
    const float* __restrict__ Vg, float* __restrict__ O)
{
    __shared__ __align__(16) float Ks[AK][HDIM];
    __shared__ __align__(16) float Vs[AK][HDIM];

    const int h  = blockIdx.y;
    const int kh = h / GROUP;
    const int q  = blockIdx.x * 128 + threadIdx.x;

    float qv[HDIM];
    {
        const float4* qp = reinterpret_cast<const float4*>(
            Q + (size_t)q * DIM + h * HDIM);
        #pragma unroll
        for (int dc = 0; dc < HDIM / 4; dc++) {
            float4 v = qp[dc];
            qv[4*dc+0] = v.x * 0.125f;
            qv[4*dc+1] = v.y * 0.125f;
            qv[4*dc+2] = v.z * 0.125f;
            qv[4*dc+3] = v.w * 0.125f;
        }
    }

    float acc[HDIM];
    #pragma unroll
    for (int d = 0; d < HDIM; d++) acc[d] = 0.f;
    float m = -1e30f, l = 0.f;

    for (int k0 = 0; k0 < SEQ; k0 += AK) {
        // Load K/V tiles (coalesced float4)
        for (int i = threadIdx.x; i < AK * (HDIM / 4); i += 128) {
            int j  = i >> 4;
            int dc = i & 15;
            size_t base = (size_t)(k0 + j) * KVDIM + kh * HDIM;
            reinterpret_cast<float4*>(Ks[j])[dc] =
                reinterpret_cast<const float4*>(Kg + base)[dc];
            reinterpret_cast<float4*>(Vs[j])[dc] =
                reinterpret_cast<const float4*>(Vg + base)[dc];
        }
        __syncthreads();

        float sc[AK];
        #pragma unroll
        for (int j = 0; j < AK; j++) {
            float s = 0.f;
            const float4* kr = reinterpret_cast<const float4*>(Ks[j]);
            #pragma unroll
            for (int dc = 0; dc < HDIM / 4; dc++) {
                float4 kv4 = kr[dc];
                s += qv[4*dc+0] * kv4.x;
                s += qv[4*dc+1] * kv4.y;
                s += qv[4*dc+2] * kv4.z;
                s += qv[4*dc+3] * kv4.w;
            }
            sc[j] = s;
        }

        float tmax = sc[0];
        #pragma unroll
        for (int j = 1; j < AK; j++) tmax = fmaxf(tmax, sc[j]);
        float mnew = fmaxf(m, tmax);
        float corr = __expf(m - mnew);
        m = mnew;
        l *= corr;
        #pragma unroll
        for (int d = 0; d < HDIM; d++) acc[d] *= corr;

        #pragma unroll
        for (int j = 0; j < AK; j++) {
            float p = __expf(sc[j] - m);
            l += p;
            const float4* vr = reinterpret_cast<const float4*>(Vs[j]);
            #pragma unroll
            for (int dc = 0; dc < HDIM / 4; dc++) {
                float4 vv4 = vr[dc];
                acc[4*dc+0] += p * vv4.x;
                acc[4*dc+1] += p * vv4.y;
                acc[4*dc+2] += p * vv4.z;
                acc[4*dc+3] += p * vv4.w;
            }
        }
        __syncthreads();
    }

    float inv_l = 1.f / l;
    float* op = O + (size_t)q * DIM + h * HDIM;
    #pragma unroll
    for (int dc = 0; dc < HDIM / 4; dc++) {
        float4 v = make_float4(acc[4*dc+0] * inv_l, acc[4*dc+1] * inv_l,
                               acc[4*dc+2] * inv_l, acc[4*dc+3] * inv_l);
        *reinterpret_cast<float4*>(op + 4 * dc) = v;
    }
}

// ---------------------------------------------------------------------------
// Launch
// ---------------------------------------------------------------------------
extern "C" void kernel_launch(void* const* d_in, const int* in_sizes, int n_in,
                              void* d_out, int out_size)
{
    const float* x  = (const float*)d_in[0];
    const float* wq = (const float*)d_in[1];
    const float* wk = (const float*)d_in[2];
    const float* wv = (const float*)d_in[3];
    const float* wo = (const float*)d_in[4];
    float* out = (float*)d_out;

    float *Qb, *Kb, *Vb, *Ob;
    cudaGetSymbolAddress((void**)&Qb, g_Q);
    cudaGetSymbolAddress((void**)&Kb, g_K);
    cudaGetSymbolAddress((void**)&Vb, g_V);
    cudaGetSymbolAddress((void**)&Ob, g_O);

    // Q = x @ wq
    sgemm_kernel<<<dim3(DIM / BN, SEQ / BM), 256>>>(x, wq, Qb, SEQ, DIM, DIM);
    // K = x @ wk, V = x @ wv
    sgemm_kernel<<<dim3(KVDIM / BN, SEQ / BM), 256>>>(x, wk, Kb, SEQ, KVDIM, DIM);
    sgemm_kernel<<<dim3(KVDIM / BN, SEQ / BM), 256>>>(x, wv, Vb, SEQ, KVDIM, DIM);
    // RoPE
    rope_kernel<<<SEQ, NHEADS * 32>>>(Qb, DIM);
    rope_kernel<<<SEQ, NKV * 32>>>(Kb, KVDIM);
    // Attention
    attn_kernel<<<dim3(SEQ / 128, NHEADS), 128>>>(Qb, Kb, Vb, Ob);
    // out = attn_out @ wo
    sgemm_kernel<<<dim3(DIM / BN, SEQ / BM), 256>>>(Ob, wo, out, SEQ, DIM, DIM);
}

// round 3
// speedup vs baseline: 1.3477x; 1.3477x over previous
#include <cuda_runtime.h>
#include <cuda_bf16.h>
#include <cstdint>

// ---------------------------------------------------------------------------
// GroupedQueryAttention — Round 3: portable HMMA (mma.sync bf16, 3-term split)
// GEMMs + fp32 flash attention. No sm_103a-only instructions.
// ---------------------------------------------------------------------------

#define SEQ      2048
#define DIM      2048
#define KVDIM    512
#define NHEADS   32
#define NKV      8
#define GROUP    4
#define HDIM     64
#define GK       2048    // inner dim of every GEMM

// fp32 scratch
__device__ float g_Q[SEQ * DIM];
__device__ float g_K[SEQ * KVDIM];
__device__ float g_V[SEQ * KVDIM];
__device__ float g_O[SEQ * DIM];

// bf16 split scratch (A: row-major [M,K]; B: transposed [N,K])
__device__ __nv_bfloat16 g_xh[SEQ * DIM];
__device__ __nv_bfloat16 g_xl[SEQ * DIM];
__device__ __nv_bfloat16 g_Oh[SEQ * DIM];
__device__ __nv_bfloat16 g_Ol[SEQ * DIM];
__device__ __nv_bfloat16 g_wqhT[DIM * DIM];
__device__ __nv_bfloat16 g_wqlT[DIM * DIM];
__device__ __nv_bfloat16 g_wkhT[KVDIM * DIM];
__device__ __nv_bfloat16 g_wklT[KVDIM * DIM];
__device__ __nv_bfloat16 g_wvhT[KVDIM * DIM];
__device__ __nv_bfloat16 g_wvlT[KVDIM * DIM];
__device__ __nv_bfloat16 g_wohT[DIM * DIM];
__device__ __nv_bfloat16 g_wolT[DIM * DIM];

// ---------------------------------------------------------------------------
// Portable PTX helpers
// ---------------------------------------------------------------------------
__device__ __forceinline__ uint32_t smem_u32(const void* p) {
    uint32_t a;
    asm("{ .reg .u64 t; cvta.to.shared.u64 t, %1; cvt.u32.u64 %0, t; }"
        : "=r"(a) : "l"(p));
    return a;
}

#define CP_ASYNC16(dst_u32, src_ptr) \
    asm volatile("cp.async.cg.shared.global [%0], [%1], 16;" \
                 :: "r"(dst_u32), "l"(src_ptr))
#define CP_COMMIT() asm volatile("cp.async.commit_group;" ::: "memory")
#define CP_WAIT2()  asm volatile("cp.async.wait_group 2;" ::: "memory")
#define CP_WAIT0()  asm volatile("cp.async.wait_group 0;" ::: "memory")

__device__ __forceinline__ void ldsm_x4(uint32_t* r, uint32_t addr) {
    asm volatile("ldmatrix.sync.aligned.m8n8.x4.shared.b16 {%0,%1,%2,%3}, [%4];"
                 : "=r"(r[0]), "=r"(r[1]), "=r"(r[2]), "=r"(r[3]) : "r"(addr));
}

__device__ __forceinline__ void mma16816(float* c, const uint32_t* a,
                                         const uint32_t* b) {
    asm volatile(
        "mma.sync.aligned.m16n8k16.row.col.f32.bf16.bf16.f32 "
        "{%0,%1,%2,%3}, {%4,%5,%6,%7}, {%8,%9}, {%0,%1,%2,%3};"
        : "+f"(c[0]), "+f"(c[1]), "+f"(c[2]), "+f"(c[3])
        : "r"(a[0]), "r"(a[1]), "r"(a[2]), "r"(a[3]), "r"(b[0]), "r"(b[1]));
}

// ---------------------------------------------------------------------------
// HMMA GEMM: C[M,N] fp32 = Ah*Bh + Ah*Bl + Al*Bh
//   A split row-major [M, GK], B split transposed [N, GK]
//   CTA tile 128x128, 8 warps (4x2) of 32x64, K-chunk 32, 3-stage cp.async.
// Smem per operand tile: 128 rows x 40 halves (80B padded rows).
// ---------------------------------------------------------------------------
#define KCH      32
#define LDS_H    40                       // padded halves per row
#define TILE_B   (128 * LDS_H * 2)        // 10240 bytes
#define STAGE_B  (4 * TILE_B)             // Ah, Al, Bh, Bl
#define NSTAGE   3
#define GEMM_SMEM (NSTAGE * STAGE_B)      // 122880 bytes

__device__ __forceinline__ void issue_stage(
    const __nv_bfloat16* __restrict__ Ah, const __nv_bfloat16* __restrict__ Al,
    const __nv_bfloat16* __restrict__ Bh, const __nv_bfloat16* __restrict__ Bl,
    int m0, int n0, int k0, char* s, uint32_t s_u32, int tid)
{
    const __nv_bfloat16* gp[4] = { Ah, Al, Bh, Bl };
    const int r0[4] = { m0, m0, n0, n0 };
    #pragma unroll
    for (int p = 0; p < 4; p++) {
        #pragma unroll
        for (int i = 0; i < 2; i++) {
            int e   = tid + i * 256;
            int row = e >> 2;
            int q   = e & 3;
            const __nv_bfloat16* src =
                gp[p] + (size_t)(r0[p] + row) * GK + k0 + q * 8;
            uint32_t dst = s_u32 + p * TILE_B + row * (LDS_H * 2) + q * 16;
            CP_ASYNC16(dst, src);
        }
    }
    (void)s;
}

__global__ void __launch_bounds__(256, 1)
gemm3_kernel(const __nv_bfloat16* __restrict__ Ah,
             const __nv_bfloat16* __restrict__ Al,
             const __nv_bfloat16* __restrict__ BhT,
             const __nv_bfloat16* __restrict__ BlT,
             float* __restrict__ C, int ldc)
{
    extern __shared__ char smem[];
    const uint32_t sm0 = smem_u32(smem);
    const int tid  = threadIdx.x;
    const int wid  = tid >> 5;
    const int lane = tid & 31;
    const int wm   = wid & 3;            // 0..3 -> m block of 32
    const int wn   = wid >> 2;           // 0..1 -> n block of 64
    const int m0   = blockIdx.y * 128;
    const int n0   = blockIdx.x * 128;

    const int NC = GK / KCH;             // 64 chunks

    // ldmatrix lane addressing (shared by A and B tiles)
    const int lrow = (lane & 7) + ((lane >> 3) & 1) * 8;
    const int lcol = (lane >> 4) * 8;

    float acc[2][8][4];
    #pragma unroll
    for (int mt = 0; mt < 2; mt++)
        #pragma unroll
        for (int n8 = 0; n8 < 8; n8++)
            #pragma unroll
            for (int j = 0; j < 4; j++) acc[mt][n8][j] = 0.f;

    // prologue: stages 0,1 <- chunks 0,1
    issue_stage(Ah, Al, BhT, BlT, m0, n0, 0 * KCH, smem, sm0, tid);
    CP_COMMIT();
    issue_stage(Ah, Al, BhT, BlT, m0, n0, 1 * KCH, smem, sm0 + STAGE_B, tid);
    CP_COMMIT();

    for (int c = 0; c < NC; c++) {
        if (c + 2 < NC) {
            issue_stage(Ah, Al, BhT, BlT, m0, n0, (c + 2) * KCH,
                        smem, sm0 + ((c + 2) % NSTAGE) * STAGE_B, tid);
            CP_COMMIT();
            CP_WAIT2();
        } else {
            CP_WAIT0();
        }
        __syncthreads();

        const uint32_t sb  = sm0 + (c % NSTAGE) * STAGE_B;
        const uint32_t sAh = sb + 0 * TILE_B;
        const uint32_t sAl = sb + 1 * TILE_B;
        const uint32_t sBh = sb + 2 * TILE_B;
        const uint32_t sBl = sb + 3 * TILE_B;

        #pragma unroll
        for (int kk = 0; kk < 2; kk++) {
            uint32_t ah[2][4], al[2][4], bh[8][2], bl[8][2];
            #pragma unroll
            for (int mt = 0; mt < 2; mt++) {
                uint32_t off =
                    (uint32_t)((wm * 32 + mt * 16 + lrow) * LDS_H + kk * 16 + lcol) * 2;
                ldsm_x4(ah[mt], sAh + off);
                ldsm_x4(al[mt], sAl + off);
            }
            #pragma unroll
            for (int nt = 0; nt < 4; nt++) {
                uint32_t off =
                    (uint32_t)((wn * 64 + nt * 16 + lrow) * LDS_H + kk * 16 + lcol) * 2;
                uint32_t t[4];
                ldsm_x4(t, sBh + off);
                bh[2 * nt][0]     = t[0]; bh[2 * nt][1]     = t[2];
                bh[2 * nt + 1][0] = t[1]; bh[2 * nt + 1][1] = t[3];
                ldsm_x4(t, sBl + off);
                bl[2 * nt][0]     = t[0]; bl[2 * nt][1]     = t[2];
                bl[2 * nt + 1][0] = t[1]; bl[2 * nt + 1][1] = t[3];
            }
            #pragma unroll
            for (int mt = 0; mt < 2; mt++)
                #pragma unroll
                for (int n8 = 0; n8 < 8; n8++) {
                    mma16816(acc[mt][n8], ah[mt], bh[n8]);
                    mma16816(acc[mt][n8], ah[mt], bl[n8]);
                    mma16816(acc[mt][n8], al[mt], bh[n8]);
                }
        }
        __syncthreads();
    }

    // epilogue
    const int cr = lane >> 2;
    const int cc = (lane & 3) * 2;
    #pragma unroll
    for (int mt = 0; mt < 2; mt++) {
        #pragma unroll
        for (int n8 = 0; n8 < 8; n8++) {
            float* base = C + (size_t)(m0 + wm * 32 + mt * 16 + cr) * ldc
                            + n0 + wn * 64 + n8 * 8 + cc;
            *reinterpret_cast<float2*>(base) =
                make_float2(acc[mt][n8][0], acc[mt][n8][1]);
            *reinterpret_cast<float2*>(base + 8 * (size_t)ldc) =
                make_float2(acc[mt][n8][2], acc[mt][n8][3]);
        }
    }
}

// ---------------------------------------------------------------------------
// Split fp32 -> bf16 hi/lo
// ---------------------------------------------------------------------------
__global__ void split_kernel(const float* __restrict__ in,
                             __nv_bfloat16* __restrict__ hi,
                             __nv_bfloat16* __restrict__ lo)
{
    int i = (blockIdx.x * 256 + threadIdx.x) * 4;
    float4 v = *reinterpret_cast<const float4*>(in + i);
    float vv[4] = { v.x, v.y, v.z, v.w };
    __nv_bfloat16 h[4], l[4];
    #pragma unroll
    for (int j = 0; j < 4; j++) {
        h[j] = __float2bfloat16(vv[j]);
        l[j] = __float2bfloat16(vv[j] - __bfloat162float(h[j]));
    }
    *reinterpret_cast<uint2*>(hi + i) = *reinterpret_cast<uint2*>(h);
    *reinterpret_cast<uint2*>(lo + i) = *reinterpret_cast<uint2*>(l);
}

// ---------------------------------------------------------------------------
// Transpose + split: w[K,N] fp32 -> hiT/loT [N,K] bf16
// ---------------------------------------------------------------------------
__global__ void tsplit_kernel(const float* __restrict__ w,
                              __nv_bfloat16* __restrict__ hiT,
                              __nv_bfloat16* __restrict__ loT,
                              int K, int N)
{
    __shared__ float t[32][33];
    const int k0 = blockIdx.y * 32;
    const int n0 = blockIdx.x * 32;
    const int tx = threadIdx.x, ty = threadIdx.y;  // (32, 8)
    #pragma unroll
    for (int r = 0; r < 4; r++)
        t[ty + 8 * r][tx] = w[(size_t)(k0 + ty + 8 * r) * N + n0 + tx];
    __syncthreads();
    #pragma unroll
    for (int r = 0; r < 4; r++) {
        int row = ty + 8 * r;
        float v = t[tx][row];
        __nv_bfloat16 h = __float2bfloat16(v);
        __nv_bfloat16 l = __float2bfloat16(v - __bfloat162float(h));
        size_t o = (size_t)(n0 + row) * K + k0 + tx;
        hiT[o] = h;
        loT[o] = l;
    }
}

// ---------------------------------------------------------------------------
// RoPE in-place
// ---------------------------------------------------------------------------
__global__ void rope_kernel(float* __restrict__ buf, int stride)
{
    int s = blockIdx.x;
    int h = threadIdx.x >> 5;
    int d = threadIdx.x & 31;
    float inv = expf(-(float)d * (logf(10000.0f) / 32.0f));
    float ang = (float)s * inv;
    float c, sn;
    sincosf(ang, &sn, &c);
    float* p = buf + (size_t)s * stride + h * HDIM;
    float x1 = p[d];
    float x2 = p[d + 32];
    p[d]      = x1 * c - x2 * sn;
    p[d + 32] = x2 * c + x1 * sn;
}

// ---------------------------------------------------------------------------
// Flash attention (fp32, unchanged)
// ---------------------------------------------------------------------------
#define AK 16

__global__ void __launch_bounds__(128) attn_kernel(
    const float* __restrict__ Q, const float* __restrict__ Kg,
    const float* __restrict__ Vg, float* __restrict__ O)
{
    __shared__ __align__(16) float Ks[AK][HDIM];
    __shared__ __align__(16) float Vs[AK][HDIM];

    const int h  = blockIdx.y;
    const int kh = h / GROUP;
    const int q  = blockIdx.x * 128 + threadIdx.x;

    float qv[HDIM];
    {
        const float4* qp = reinterpret_cast<const float4*>(
            Q + (size_t)q * DIM + h * HDIM);
        #pragma unroll
        for (int dc = 0; dc < HDIM / 4; dc++) {
            float4 v = qp[dc];
            qv[4*dc+0] = v.x * 0.125f;
            qv[4*dc+1] = v.y * 0.125f;
            qv[4*dc+2] = v.z * 0.125f;
            qv[4*dc+3] = v.w * 0.125f;
        }
    }

    float acc[HDIM];
    #pragma unroll
    for (int d = 0; d < HDIM; d++) acc[d] = 0.f;
    float m = -1e30f, l = 0.f;

    for (int k0 = 0; k0 < SEQ; k0 += AK) {
        for (int i = threadIdx.x; i < AK * (HDIM / 4); i += 128) {
            int j  = i >> 4;
            int dc = i & 15;
            size_t base = (size_t)(k0 + j) * KVDIM + kh * HDIM;
            reinterpret_cast<float4*>(Ks[j])[dc] =
                reinterpret_cast<const float4*>(Kg + base)[dc];
            reinterpret_cast<float4*>(Vs[j])[dc] =
                reinterpret_cast<const float4*>(Vg + base)[dc];
        }
        __syncthreads();

        float sc[AK];
        #pragma unroll
        for (int j = 0; j < AK; j++) {
            float s = 0.f;
            const float4* kr = reinterpret_cast<const float4*>(Ks[j]);
            #pragma unroll
            for (int dc = 0; dc < HDIM / 4; dc++) {
                float4 kv4 = kr[dc];
                s += qv[4*dc+0] * kv4.x;
                s += qv[4*dc+1] * kv4.y;
                s += qv[4*dc+2] * kv4.z;
                s += qv[4*dc+3] * kv4.w;
            }
            sc[j] = s;
        }

        float tmax = sc[0];
        #pragma unroll
        for (int j = 1; j < AK; j++) tmax = fmaxf(tmax, sc[j]);
        float mnew = fmaxf(m, tmax);
        float corr = __expf(m - mnew);
        m = mnew;
        l *= corr;
        #pragma unroll
        for (int d = 0; d < HDIM; d++) acc[d] *= corr;

        #pragma unroll
        for (int j = 0; j < AK; j++) {
            float p = __expf(sc[j] - m);
            l += p;
            const float4* vr = reinterpret_cast<const float4*>(Vs[j]);
            #pragma unroll
            for (int dc = 0; dc < HDIM / 4; dc++) {
                float4 vv4 = vr[dc];
                acc[4*dc+0] += p * vv4.x;
                acc[4*dc+1] += p * vv4.y;
                acc[4*dc+2] += p * vv4.z;
                acc[4*dc+3] += p * vv4.w;
            }
        }
        __syncthreads();
    }

    float inv_l = 1.f / l;
    float* op = O + (size_t)q * DIM + h * HDIM;
    #pragma unroll
    for (int dc = 0; dc < HDIM / 4; dc++) {
        float4 v = make_float4(acc[4*dc+0] * inv_l, acc[4*dc+1] * inv_l,
                               acc[4*dc+2] * inv_l, acc[4*dc+3] * inv_l);
        *reinterpret_cast<float4*>(op + 4 * dc) = v;
    }
}

// ---------------------------------------------------------------------------
// Launch
// ---------------------------------------------------------------------------
extern "C" void kernel_launch(void* const* d_in, const int* in_sizes, int n_in,
                              void* d_out, int out_size)
{
    const float* x  = (const float*)d_in[0];
    const float* wq = (const float*)d_in[1];
    const float* wk = (const float*)d_in[2];
    const float* wv = (const float*)d_in[3];
    const float* wo = (const float*)d_in[4];
    float* out = (float*)d_out;

    float *Qb, *Kb, *Vb, *Ob;
    cudaGetSymbolAddress((void**)&Qb, g_Q);
    cudaGetSymbolAddress((void**)&Kb, g_K);
    cudaGetSymbolAddress((void**)&Vb, g_V);
    cudaGetSymbolAddress((void**)&Ob, g_O);

    __nv_bfloat16 *xh, *xl, *Oh, *Ol;
    __nv_bfloat16 *wqh, *wql, *wkh, *wkl, *wvh, *wvl, *woh, *wol;
    cudaGetSymbolAddress((void**)&xh, g_xh);
    cudaGetSymbolAddress((void**)&xl, g_xl);
    cudaGetSymbolAddress((void**)&Oh, g_Oh);
    cudaGetSymbolAddress((void**)&Ol, g_Ol);
    cudaGetSymbolAddress((void**)&wqh, g_wqhT);
    cudaGetSymbolAddress((void**)&wql, g_wqlT);
    cudaGetSymbolAddress((void**)&wkh, g_wkhT);
    cudaGetSymbolAddress((void**)&wkl, g_wklT);
    cudaGetSymbolAddress((void**)&wvh, g_wvhT);
    cudaGetSymbolAddress((void**)&wvl, g_wvlT);
    cudaGetSymbolAddress((void**)&woh, g_wohT);
    cudaGetSymbolAddress((void**)&wol, g_wolT);

    cudaFuncSetAttribute(gemm3_kernel,
        cudaFuncAttributeMaxDynamicSharedMemorySize, GEMM_SMEM);

    // splits
    split_kernel<<<SEQ * DIM / 1024, 256>>>(x, xh, xl);
    tsplit_kernel<<<dim3(DIM / 32, DIM / 32), dim3(32, 8)>>>(wq, wqh, wql, DIM, DIM);
    tsplit_kernel<<<dim3(KVDIM / 32, DIM / 32), dim3(32, 8)>>>(wk, wkh, wkl, DIM, KVDIM);
    tsplit_kernel<<<dim3(KVDIM / 32, DIM / 32), dim3(32, 8)>>>(wv, wvh, wvl, DIM, KVDIM);
    tsplit_kernel<<<dim3(DIM / 32, DIM / 32), dim3(32, 8)>>>(wo, woh, wol, DIM, DIM);

    // projections (HMMA)
    gemm3_kernel<<<dim3(DIM / 128, SEQ / 128), 256, GEMM_SMEM>>>(
        xh, xl, wqh, wql, Qb, DIM);
    gemm3_kernel<<<dim3(KVDIM / 128, SEQ / 128), 256, GEMM_SMEM>>>(
        xh, xl, wkh, wkl, Kb, KVDIM);
    gemm3_kernel<<<dim3(KVDIM / 128, SEQ / 128), 256, GEMM_SMEM>>>(
        xh, xl, wvh, wvl, Vb, KVDIM);

    // RoPE
    rope_kernel<<<SEQ, NHEADS * 32>>>(Qb, DIM);
    rope_kernel<<<SEQ, NKV * 32>>>(Kb, KVDIM);

    // attention (fp32)
    attn_kernel<<<dim3(SEQ / 128, NHEADS), 128>>>(Qb, Kb, Vb, Ob);

    // output projection
    split_kernel<<<SEQ * DIM / 1024, 256>>>(Ob, Oh, Ol);
    gemm3_kernel<<<dim3(DIM / 128, SEQ / 128), 256, GEMM_SMEM>>>(
        Oh, Ol, woh, wol, out, DIM);
}

// round 4
// speedup vs baseline: 2.6574x; 1.9718x over previous
#include <cuda_runtime.h>
#include <cuda_bf16.h>
#include <cstdint>

// ---------------------------------------------------------------------------
// GroupedQueryAttention — Round 4: HMMA GEMMs + HMMA flash attention
// (3-term bf16 splits everywhere; portable mma.sync only)
// ---------------------------------------------------------------------------

#define SEQ      2048
#define DIM      2048
#define KVDIM    512
#define NHEADS   32
#define NKV      8
#define GROUP    4
#define HDIM     64
#define GK       2048

// fp32 scratch
__device__ float g_Q[SEQ * DIM];
__device__ float g_K[SEQ * KVDIM];
__device__ float g_V[SEQ * KVDIM];
__device__ float g_O[SEQ * DIM];

// bf16 split scratch
__device__ __nv_bfloat16 g_xh[SEQ * DIM];
__device__ __nv_bfloat16 g_xl[SEQ * DIM];
__device__ __nv_bfloat16 g_Oh[SEQ * DIM];
__device__ __nv_bfloat16 g_Ol[SEQ * DIM];
__device__ __nv_bfloat16 g_wqhT[DIM * DIM];
__device__ __nv_bfloat16 g_wqlT[DIM * DIM];
__device__ __nv_bfloat16 g_wkhT[KVDIM * DIM];
__device__ __nv_bfloat16 g_wklT[KVDIM * DIM];
__device__ __nv_bfloat16 g_wvhT[KVDIM * DIM];
__device__ __nv_bfloat16 g_wvlT[KVDIM * DIM];
__device__ __nv_bfloat16 g_wohT[DIM * DIM];
__device__ __nv_bfloat16 g_wolT[DIM * DIM];

// attention operands (bf16 splits)
__device__ __nv_bfloat16 g_Qh[SEQ * DIM];     // pre-scaled by 0.125
__device__ __nv_bfloat16 g_Ql[SEQ * DIM];
__device__ __nv_bfloat16 g_Kh[SEQ * KVDIM];
__device__ __nv_bfloat16 g_Kl[SEQ * KVDIM];
__device__ __nv_bfloat16 g_Vth[KVDIM * SEQ];  // V transposed: [512][2048]
__device__ __nv_bfloat16 g_Vtl[KVDIM * SEQ];

// ---------------------------------------------------------------------------
// PTX helpers (portable)
// ---------------------------------------------------------------------------
__device__ __forceinline__ uint32_t smem_u32(const void* p) {
    uint32_t a;
    asm("{ .reg .u64 t; cvta.to.shared.u64 t, %1; cvt.u32.u64 %0, t; }"
        : "=r"(a) : "l"(p));
    return a;
}

#define CP_ASYNC16(dst_u32, src_ptr) \
    asm volatile("cp.async.cg.shared.global [%0], [%1], 16;" \
                 :: "r"(dst_u32), "l"(src_ptr))
#define CP_COMMIT() asm volatile("cp.async.commit_group;" ::: "memory")
#define CP_WAIT2()  asm volatile("cp.async.wait_group 2;" ::: "memory")
#define CP_WAIT1()  asm volatile("cp.async.wait_group 1;" ::: "memory")
#define CP_WAIT0()  asm volatile("cp.async.wait_group 0;" ::: "memory")

__device__ __forceinline__ void ldsm_x4(uint32_t* r, uint32_t addr) {
    asm volatile("ldmatrix.sync.aligned.m8n8.x4.shared.b16 {%0,%1,%2,%3}, [%4];"
                 : "=r"(r[0]), "=r"(r[1]), "=r"(r[2]), "=r"(r[3]) : "r"(addr));
}

__device__ __forceinline__ void mma16816(float* c, const uint32_t* a,
                                         const uint32_t* b) {
    asm volatile(
        "mma.sync.aligned.m16n8k16.row.col.f32.bf16.bf16.f32 "
        "{%0,%1,%2,%3}, {%4,%5,%6,%7}, {%8,%9}, {%0,%1,%2,%3};"
        : "+f"(c[0]), "+f"(c[1]), "+f"(c[2]), "+f"(c[3])
        : "r"(a[0]), "r"(a[1]), "r"(a[2]), "r"(a[3]), "r"(b[0]), "r"(b[1]));
}

// split two fp32 into packed bf16x2 hi + lo (x = first arg = low half)
__device__ __forceinline__ void split2(float a, float b,
                                       uint32_t& hi, uint32_t& lo) {
    __nv_bfloat162 H = __floats2bfloat162_rn(a, b);
    float2 Hf = __bfloat1622float2(H);
    __nv_bfloat162 L = __floats2bfloat162_rn(a - Hf.x, b - Hf.y);
    hi = *reinterpret_cast<uint32_t*>(&H);
    lo = *reinterpret_cast<uint32_t*>(&L);
}

// ---------------------------------------------------------------------------
// HMMA GEMM (unchanged from R3): C = Ah*Bh + Ah*Bl + Al*Bh
// ---------------------------------------------------------------------------
#define KCH      32
#define LDS_H    40
#define TILE_B   (128 * LDS_H * 2)
#define STAGE_B  (4 * TILE_B)
#define NSTAGE   3
#define GEMM_SMEM (NSTAGE * STAGE_B)

__device__ __forceinline__ void issue_stage(
    const __nv_bfloat16* __restrict__ Ah, const __nv_bfloat16* __restrict__ Al,
    const __nv_bfloat16* __restrict__ Bh, const __nv_bfloat16* __restrict__ Bl,
    int m0, int n0, int k0, uint32_t s_u32, int tid)
{
    const __nv_bfloat16* gp[4] = { Ah, Al, Bh, Bl };
    const int r0[4] = { m0, m0, n0, n0 };
    #pragma unroll
    for (int p = 0; p < 4; p++) {
        #pragma unroll
        for (int i = 0; i < 2; i++) {
            int e   = tid + i * 256;
            int row = e >> 2;
            int q   = e & 3;
            const __nv_bfloat16* src =
                gp[p] + (size_t)(r0[p] + row) * GK + k0 + q * 8;
            uint32_t dst = s_u32 + p * TILE_B + row * (LDS_H * 2) + q * 16;
            CP_ASYNC16(dst, src);
        }
    }
}

__global__ void __launch_bounds__(256, 1)
gemm3_kernel(const __nv_bfloat16* __restrict__ Ah,
             const __nv_bfloat16* __restrict__ Al,
             const __nv_bfloat16* __restrict__ BhT,
             const __nv_bfloat16* __restrict__ BlT,
             float* __restrict__ C, int ldc)
{
    extern __shared__ char smem[];
    const uint32_t sm0 = smem_u32(smem);
    const int tid  = threadIdx.x;
    const int wid  = tid >> 5;
    const int lane = tid & 31;
    const int wm   = wid & 3;
    const int wn   = wid >> 2;
    const int m0   = blockIdx.y * 128;
    const int n0   = blockIdx.x * 128;
    const int NC   = GK / KCH;

    const int lrow = (lane & 7) + ((lane >> 3) & 1) * 8;
    const int lcol = (lane >> 4) * 8;

    float acc[2][8][4];
    #pragma unroll
    for (int mt = 0; mt < 2; mt++)
        #pragma unroll
        for (int n8 = 0; n8 < 8; n8++)
            #pragma unroll
            for (int j = 0; j < 4; j++) acc[mt][n8][j] = 0.f;

    issue_stage(Ah, Al, BhT, BlT, m0, n0, 0 * KCH, sm0, tid);
    CP_COMMIT();
    issue_stage(Ah, Al, BhT, BlT, m0, n0, 1 * KCH, sm0 + STAGE_B, tid);
    CP_COMMIT();

    for (int c = 0; c < NC; c++) {
        if (c + 2 < NC) {
            issue_stage(Ah, Al, BhT, BlT, m0, n0, (c + 2) * KCH,
                        sm0 + ((c + 2) % NSTAGE) * STAGE_B, tid);
            CP_COMMIT();
            CP_WAIT2();
        } else {
            CP_WAIT0();
        }
        __syncthreads();

        const uint32_t sb  = sm0 + (c % NSTAGE) * STAGE_B;
        const uint32_t sAh = sb + 0 * TILE_B;
        const uint32_t sAl = sb + 1 * TILE_B;
        const uint32_t sBh = sb + 2 * TILE_B;
        const uint32_t sBl = sb + 3 * TILE_B;

        #pragma unroll
        for (int kk = 0; kk < 2; kk++) {
            uint32_t ah[2][4], al[2][4], bh[8][2], bl[8][2];
            #pragma unroll
            for (int mt = 0; mt < 2; mt++) {
                uint32_t off =
                    (uint32_t)((wm * 32 + mt * 16 + lrow) * LDS_H + kk * 16 + lcol) * 2;
                ldsm_x4(ah[mt], sAh + off);
                ldsm_x4(al[mt], sAl + off);
            }
            #pragma unroll
            for (int nt = 0; nt < 4; nt++) {
                uint32_t off =
                    (uint32_t)((wn * 64 + nt * 16 + lrow) * LDS_H + kk * 16 + lcol) * 2;
                uint32_t t[4];
                ldsm_x4(t, sBh + off);
                bh[2 * nt][0]     = t[0]; bh[2 * nt][1]     = t[2];
                bh[2 * nt + 1][0] = t[1]; bh[2 * nt + 1][1] = t[3];
                ldsm_x4(t, sBl + off);
                bl[2 * nt][0]     = t[0]; bl[2 * nt][1]     = t[2];
                bl[2 * nt + 1][0] = t[1]; bl[2 * nt + 1][1] = t[3];
            }
            #pragma unroll
            for (int mt = 0; mt < 2; mt++)
                #pragma unroll
                for (int n8 = 0; n8 < 8; n8++) {
                    mma16816(acc[mt][n8], ah[mt], bh[n8]);
                    mma16816(acc[mt][n8], ah[mt], bl[n8]);
                    mma16816(acc[mt][n8], al[mt], bh[n8]);
                }
        }
        __syncthreads();
    }

    const int cr = lane >> 2;
    const int cc = (lane & 3) * 2;
    #pragma unroll
    for (int mt = 0; mt < 2; mt++) {
        #pragma unroll
        for (int n8 = 0; n8 < 8; n8++) {
            float* base = C + (size_t)(m0 + wm * 32 + mt * 16 + cr) * ldc
                            + n0 + wn * 64 + n8 * 8 + cc;
            *reinterpret_cast<float2*>(base) =
                make_float2(acc[mt][n8][0], acc[mt][n8][1]);
            *reinterpret_cast<float2*>(base + 8 * (size_t)ldc) =
                make_float2(acc[mt][n8][2], acc[mt][n8][3]);
        }
    }
}

// ---------------------------------------------------------------------------
// Split fp32 -> bf16 hi/lo with optional scale
// ---------------------------------------------------------------------------
__global__ void split_kernel(const float* __restrict__ in,
                             __nv_bfloat16* __restrict__ hi,
                             __nv_bfloat16* __restrict__ lo, float scale)
{
    int i = (blockIdx.x * 256 + threadIdx.x) * 4;
    float4 v = *reinterpret_cast<const float4*>(in + i);
    float vv[4] = { v.x * scale, v.y * scale, v.z * scale, v.w * scale };
    __nv_bfloat16 h[4], l[4];
    #pragma unroll
    for (int j = 0; j < 4; j++) {
        h[j] = __float2bfloat16(vv[j]);
        l[j] = __float2bfloat16(vv[j] - __bfloat162float(h[j]));
    }
    *reinterpret_cast<uint2*>(hi + i) = *reinterpret_cast<uint2*>(h);
    *reinterpret_cast<uint2*>(lo + i) = *reinterpret_cast<uint2*>(l);
}

// ---------------------------------------------------------------------------
// Transpose + split: w[K,N] fp32 -> hiT/loT [N,K] bf16
// ---------------------------------------------------------------------------
__global__ void tsplit_kernel(const float* __restrict__ w,
                              __nv_bfloat16* __restrict__ hiT,
                              __nv_bfloat16* __restrict__ loT,
                              int K, int N)
{
    __shared__ float t[32][33];
    const int k0 = blockIdx.y * 32;
    const int n0 = blockIdx.x * 32;
    const int tx = threadIdx.x, ty = threadIdx.y;
    #pragma unroll
    for (int r = 0; r < 4; r++)
        t[ty + 8 * r][tx] = w[(size_t)(k0 + ty + 8 * r) * N + n0 + tx];
    __syncthreads();
    #pragma unroll
    for (int r = 0; r < 4; r++) {
        int row = ty + 8 * r;
        float v = t[tx][row];
        __nv_bfloat16 h = __float2bfloat16(v);
        __nv_bfloat16 l = __float2bfloat16(v - __bfloat162float(h));
        size_t o = (size_t)(n0 + row) * K + k0 + tx;
        hiT[o] = h;
        loT[o] = l;
    }
}

// ---------------------------------------------------------------------------
// RoPE in-place
// ---------------------------------------------------------------------------
__global__ void rope_kernel(float* __restrict__ buf, int stride)
{
    int s = blockIdx.x;
    int h = threadIdx.x >> 5;
    int d = threadIdx.x & 31;
    float inv = expf(-(float)d * (logf(10000.0f) / 32.0f));
    float ang = (float)s * inv;
    float c, sn;
    sincosf(ang, &sn, &c);
    float* p = buf + (size_t)s * stride + h * HDIM;
    float x1 = p[d];
    float x2 = p[d + 32];
    p[d]      = x1 * c - x2 * sn;
    p[d + 32] = x2 * c + x1 * sn;
}

// ---------------------------------------------------------------------------
// HMMA flash attention
//   grid = (SEQ/64, NHEADS), 128 threads (4 warps x 16 query rows)
// ---------------------------------------------------------------------------
#define BQ     64
#define BK     64
#define PADH   72
#define ROWB   (PADH * 2)          // 144 bytes per 64-half row
#define ATILE  (64 * ROWB)         // 9216
#define ASTAGE (4 * ATILE)         // Kh,Kl,Vth,Vtl = 36864
#define SM_QH  0
#define SM_QL  ATILE
#define SM_KV  (2 * ATILE)
#define ATT_SMEM (SM_KV + 2 * ASTAGE)   // 92160

__device__ __forceinline__ void att_issue(
    uint32_t sb,
    const __nv_bfloat16* __restrict__ Kh, const __nv_bfloat16* __restrict__ Kl,
    const __nv_bfloat16* __restrict__ Vth, const __nv_bfloat16* __restrict__ Vtl,
    int k0, int kh, int tid)
{
    const size_t kbase  = (size_t)kh * HDIM;
    const size_t vtbase = (size_t)kh * HDIM * SEQ;
    #pragma unroll
    for (int i = 0; i < 4; i++) {
        int idx = tid + i * 128;
        int r = idx >> 3, q = idx & 7;
        uint32_t so = (uint32_t)(r * ROWB + q * 16);
        CP_ASYNC16(sb + 0 * ATILE + so,
                   Kh + (size_t)(k0 + r) * KVDIM + kbase + q * 8);
        CP_ASYNC16(sb + 1 * ATILE + so,
                   Kl + (size_t)(k0 + r) * KVDIM + kbase + q * 8);
        CP_ASYNC16(sb + 2 * ATILE + so,
                   Vth + vtbase + (size_t)r * SEQ + k0 + q * 8);
        CP_ASYNC16(sb + 3 * ATILE + so,
                   Vtl + vtbase + (size_t)r * SEQ + k0 + q * 8);
    }
}

__global__ void __launch_bounds__(128)
attn_mma_kernel(const __nv_bfloat16* __restrict__ Qh,
                const __nv_bfloat16* __restrict__ Ql,
                const __nv_bfloat16* __restrict__ Kh,
                const __nv_bfloat16* __restrict__ Kl,
                const __nv_bfloat16* __restrict__ Vth,
                const __nv_bfloat16* __restrict__ Vtl,
                float* __restrict__ O)
{
    extern __shared__ char smem[];
    const uint32_t s0 = smem_u32(smem);
    const int tid = threadIdx.x, wid = tid >> 5, lane = tid & 31;
    const int h  = blockIdx.y;
    const int kh = h / GROUP;
    const int q0 = blockIdx.x * BQ;
    const int lrow = (lane & 7) + ((lane >> 3) & 1) * 8;
    const int lcol = (lane >> 4) * 8;
    const int gr = lane >> 2, tg = lane & 3;
    const int NT = SEQ / BK;

    // prologue: Q tiles + KV tile 0 (one cp.async group)
    #pragma unroll
    for (int i = 0; i < 4; i++) {
        int idx = tid + i * 128;
        int r = idx >> 3, q = idx & 7;
        uint32_t so = (uint32_t)(r * ROWB + q * 16);
        CP_ASYNC16(s0 + SM_QH + so,
                   Qh + (size_t)(q0 + r) * DIM + h * HDIM + q * 8);
        CP_ASYNC16(s0 + SM_QL + so,
                   Ql + (size_t)(q0 + r) * DIM + h * HDIM + q * 8);
    }
    att_issue(s0 + SM_KV, Kh, Kl, Vth, Vtl, 0, kh, tid);
    CP_COMMIT();
    CP_WAIT0();
    __syncthreads();

    // Q fragments (resident)
    uint32_t qfh[4][4], qfl[4][4];
    #pragma unroll
    for (int kc = 0; kc < 4; kc++) {
        uint32_t off = (uint32_t)((wid * 16 + lrow) * ROWB + (kc * 16 + lcol) * 2);
        ldsm_x4(qfh[kc], s0 + SM_QH + off);
        ldsm_x4(qfl[kc], s0 + SM_QL + off);
    }

    float acc[8][4];
    #pragma unroll
    for (int j = 0; j < 8; j++)
        #pragma unroll
        for (int i = 0; i < 4; i++) acc[j][i] = 0.f;
    float m0 = -1e30f, m1 = -1e30f, l0 = 0.f, l1 = 0.f;

    for (int c = 0; c < NT; c++) {
        if (c + 1 < NT) {
            att_issue(s0 + SM_KV + ((c + 1) & 1) * ASTAGE,
                      Kh, Kl, Vth, Vtl, (c + 1) * BK, kh, tid);
            CP_COMMIT();
            CP_WAIT1();
        } else {
            CP_WAIT0();
        }
        __syncthreads();

        const uint32_t sb  = s0 + SM_KV + (c & 1) * ASTAGE;
        const uint32_t sKh = sb + 0 * ATILE;
        const uint32_t sKl = sb + 1 * ATILE;
        const uint32_t sVh = sb + 2 * ATILE;
        const uint32_t sVl = sb + 3 * ATILE;

        // S = Qh*Kh + Qh*Kl + Ql*Kh   (scores, fp32 fragments)
        float s[8][4];
        #pragma unroll
        for (int j = 0; j < 8; j++)
            #pragma unroll
            for (int i = 0; i < 4; i++) s[j][i] = 0.f;

        #pragma unroll
        for (int kc = 0; kc < 4; kc++) {
            #pragma unroll
            for (int nt = 0; nt < 4; nt++) {
                uint32_t off = (uint32_t)((nt * 16 + lrow) * ROWB + (kc * 16 + lcol) * 2);
                uint32_t th[4], tl[4];
                ldsm_x4(th, sKh + off);
                ldsm_x4(tl, sKl + off);
                uint32_t b0h[2] = { th[0], th[2] }, b1h[2] = { th[1], th[3] };
                uint32_t b0l[2] = { tl[0], tl[2] }, b1l[2] = { tl[1], tl[3] };
                mma16816(s[2 * nt],     qfh[kc], b0h);
                mma16816(s[2 * nt],     qfh[kc], b0l);
                mma16816(s[2 * nt],     qfl[kc], b0h);
                mma16816(s[2 * nt + 1], qfh[kc], b1h);
                mma16816(s[2 * nt + 1], qfh[kc], b1l);
                mma16816(s[2 * nt + 1], qfl[kc], b1h);
            }
        }

        // online softmax
        float tm0 = -1e30f, tm1 = -1e30f;
        #pragma unroll
        for (int j = 0; j < 8; j++) {
            tm0 = fmaxf(tm0, fmaxf(s[j][0], s[j][1]));
            tm1 = fmaxf(tm1, fmaxf(s[j][2], s[j][3]));
        }
        tm0 = fmaxf(tm0, __shfl_xor_sync(0xffffffffu, tm0, 1));
        tm0 = fmaxf(tm0, __shfl_xor_sync(0xffffffffu, tm0, 2));
        tm1 = fmaxf(tm1, __shfl_xor_sync(0xffffffffu, tm1, 1));
        tm1 = fmaxf(tm1, __shfl_xor_sync(0xffffffffu, tm1, 2));

        float nm0 = fmaxf(m0, tm0), nm1 = fmaxf(m1, tm1);
        float corr0 = __expf(m0 - nm0), corr1 = __expf(m1 - nm1);
        m0 = nm0; m1 = nm1;

        float sum0 = 0.f, sum1 = 0.f;
        #pragma unroll
        for (int j = 0; j < 8; j++) {
            s[j][0] = __expf(s[j][0] - m0);
            s[j][1] = __expf(s[j][1] - m0);
            s[j][2] = __expf(s[j][2] - m1);
            s[j][3] = __expf(s[j][3] - m1);
            sum0 += s[j][0] + s[j][1];
            sum1 += s[j][2] + s[j][3];
        }
        sum0 += __shfl_xor_sync(0xffffffffu, sum0, 1);
        sum0 += __shfl_xor_sync(0xffffffffu, sum0, 2);
        sum1 += __shfl_xor_sync(0xffffffffu, sum1, 1);
        sum1 += __shfl_xor_sync(0xffffffffu, sum1, 2);
        l0 = l0 * corr0 + sum0;
        l1 = l1 * corr1 + sum1;

        #pragma unroll
        for (int j = 0; j < 8; j++) {
            acc[j][0] *= corr0; acc[j][1] *= corr0;
            acc[j][2] *= corr1; acc[j][3] *= corr1;
        }

        // O += Ph*Vh + Ph*Vl + Pl*Vh
        #pragma unroll
        for (int kc = 0; kc < 4; kc++) {
            uint32_t aph[4], apl[4];
            split2(s[2 * kc][0],     s[2 * kc][1],     aph[0], apl[0]);
            split2(s[2 * kc][2],     s[2 * kc][3],     aph[1], apl[1]);
            split2(s[2 * kc + 1][0], s[2 * kc + 1][1], aph[2], apl[2]);
            split2(s[2 * kc + 1][2], s[2 * kc + 1][3], aph[3], apl[3]);
            #pragma unroll
            for (int nt = 0; nt < 4; nt++) {
                uint32_t off = (uint32_t)((nt * 16 + lrow) * ROWB + (kc * 16 + lcol) * 2);
                uint32_t th[4], tl[4];
                ldsm_x4(th, sVh + off);
                ldsm_x4(tl, sVl + off);
                uint32_t b0h[2] = { th[0], th[2] }, b1h[2] = { th[1], th[3] };
                uint32_t b0l[2] = { tl[0], tl[2] }, b1l[2] = { tl[1], tl[3] };
                mma16816(acc[2 * nt],     aph, b0h);
                mma16816(acc[2 * nt],     aph, b0l);
                mma16816(acc[2 * nt],     apl, b0h);
                mma16816(acc[2 * nt + 1], aph, b1h);
                mma16816(acc[2 * nt + 1], aph, b1l);
                mma16816(acc[2 * nt + 1], apl, b1h);
            }
        }
        __syncthreads();
    }

    const float inv0 = 1.f / l0, inv1 = 1.f / l1;
    #pragma unroll
    for (int j = 0; j < 8; j++) {
        float* r0p = O + (size_t)(q0 + wid * 16 + gr) * DIM + h * HDIM + j * 8 + tg * 2;
        float* r1p = r0p + 8 * (size_t)DIM;
        *reinterpret_cast<float2*>(r0p) =
            make_float2(acc[j][0] * inv0, acc[j][1] * inv0);
        *reinterpret_cast<float2*>(r1p) =
            make_float2(acc[j][2] * inv1, acc[j][3] * inv1);
    }
}

// ---------------------------------------------------------------------------
// Transpose + split V: V[2048,512] fp32 -> Vt hi/lo [512][2048] bf16
// ---------------------------------------------------------------------------
__global__ void vtsplit_kernel(const float* __restrict__ V,
                               __nv_bfloat16* __restrict__ Vth,
                               __nv_bfloat16* __restrict__ Vtl)
{
    __shared__ float t[32][33];
    const int sB = blockIdx.x * 32;   // seq
    const int dB = blockIdx.y * 32;   // kvdim
    const int tx = threadIdx.x, ty = threadIdx.y;
    #pragma unroll
    for (int r = 0; r < 4; r++)
        t[ty + 8 * r][tx] = V[(size_t)(sB + ty + 8 * r) * KVDIM + dB + tx];
    __syncthreads();
    #pragma unroll
    for (int r = 0; r < 4; r++) {
        int dd = ty + 8 * r;
        float v = t[tx][dd];          // = V[sB+tx][dB+dd]
        __nv_bfloat16 h = __float2bfloat16(v);
        __nv_bfloat16 l = __float2bfloat16(v - __bfloat162float(h));
        size_t o = (size_t)(dB + dd) * SEQ + sB + tx;
        Vth[o] = h;
        Vtl[o] = l;
    }
}

// ---------------------------------------------------------------------------
// Launch
// ---------------------------------------------------------------------------
extern "C" void kernel_launch(void* const* d_in, const int* in_sizes, int n_in,
                              void* d_out, int out_size)
{
    const float* x  = (const float*)d_in[0];
    const float* wq = (const float*)d_in[1];
    const float* wk = (const float*)d_in[2];
    const float* wv = (const float*)d_in[3];
    const float* wo = (const float*)d_in[4];
    float* out = (float*)d_out;

    float *Qb, *Kb, *Vb, *Ob;
    cudaGetSymbolAddress((void**)&Qb, g_Q);
    cudaGetSymbolAddress((void**)&Kb, g_K);
    cudaGetSymbolAddress((void**)&Vb, g_V);
    cudaGetSymbolAddress((void**)&Ob, g_O);

    __nv_bfloat16 *xh, *xl, *Oh, *Ol;
    __nv_bfloat16 *wqh, *wql, *wkh, *wkl, *wvh, *wvl, *woh, *wol;
    __nv_bfloat16 *qsh, *qsl, *ksh, *ksl, *vth, *vtl;
    cudaGetSymbolAddress((void**)&xh, g_xh);
    cudaGetSymbolAddress((void**)&xl, g_xl);
    cudaGetSymbolAddress((void**)&Oh, g_Oh);
    cudaGetSymbolAddress((void**)&Ol, g_Ol);
    cudaGetSymbolAddress((void**)&wqh, g_wqhT);
    cudaGetSymbolAddress((void**)&wql, g_wqlT);
    cudaGetSymbolAddress((void**)&wkh, g_wkhT);
    cudaGetSymbolAddress((void**)&wkl, g_wklT);
    cudaGetSymbolAddress((void**)&wvh, g_wvhT);
    cudaGetSymbolAddress((void**)&wvl, g_wvlT);
    cudaGetSymbolAddress((void**)&woh, g_wohT);
    cudaGetSymbolAddress((void**)&wol, g_wolT);
    cudaGetSymbolAddress((void**)&qsh, g_Qh);
    cudaGetSymbolAddress((void**)&qsl, g_Ql);
    cudaGetSymbolAddress((void**)&ksh, g_Kh);
    cudaGetSymbolAddress((void**)&ksl, g_Kl);
    cudaGetSymbolAddress((void**)&vth, g_Vth);
    cudaGetSymbolAddress((void**)&vtl, g_Vtl);

    cudaFuncSetAttribute(gemm3_kernel,
        cudaFuncAttributeMaxDynamicSharedMemorySize, GEMM_SMEM);
    cudaFuncSetAttribute(attn_mma_kernel,
        cudaFuncAttributeMaxDynamicSharedMemorySize, ATT_SMEM);

    // input splits
    split_kernel<<<SEQ * DIM / 1024, 256>>>(x, xh, xl, 1.0f);
    tsplit_kernel<<<dim3(DIM / 32, DIM / 32), dim3(32, 8)>>>(wq, wqh, wql, DIM, DIM);
    tsplit_kernel<<<dim3(KVDIM / 32, DIM / 32), dim3(32, 8)>>>(wk, wkh, wkl, DIM, KVDIM);
    tsplit_kernel<<<dim3(KVDIM / 32, DIM / 32), dim3(32, 8)>>>(wv, wvh, wvl, DIM, KVDIM);
    tsplit_kernel<<<dim3(DIM / 32, DIM / 32), dim3(32, 8)>>>(wo, woh, wol, DIM, DIM);

    // projections (HMMA)
    gemm3_kernel<<<dim3(DIM / 128, SEQ / 128), 256, GEMM_SMEM>>>(
        xh, xl, wqh, wql, Qb, DIM);
    gemm3_kernel<<<dim3(KVDIM / 128, SEQ / 128), 256, GEMM_SMEM>>>(
        xh, xl, wkh, wkl, Kb, KVDIM);
    gemm3_kernel<<<dim3(KVDIM / 128, SEQ / 128), 256, GEMM_SMEM>>>(
        xh, xl, wvh, wvl, Vb, KVDIM);

    // RoPE (fp32)
    rope_kernel<<<SEQ, NHEADS * 32>>>(Qb, DIM);
    rope_kernel<<<SEQ, NKV * 32>>>(Kb, KVDIM);

    // attention operand splits
    split_kernel<<<SEQ * DIM / 1024, 256>>>(Qb, qsh, qsl, 0.125f);
    split_kernel<<<SEQ * KVDIM / 1024, 256>>>(Kb, ksh, ksl, 1.0f);
    vtsplit_kernel<<<dim3(SEQ / 32, KVDIM / 32), dim3(32, 8)>>>(Vb, vth, vtl);

    // HMMA flash attention
    attn_mma_kernel<<<dim3(SEQ / BQ, NHEADS), 128, ATT_SMEM>>>(
        qsh, qsl, ksh, ksl, vth, vtl, Ob);

    // output projection
    split_kernel<<<SEQ * DIM / 1024, 256>>>(Ob, Oh, Ol, 1.0f);
    gemm3_kernel<<<dim3(DIM / 128, SEQ / 128), 256, GEMM_SMEM>>>(
        Oh, Ol, woh, wol, out, DIM);
}

// round 5
// speedup vs baseline: 2.9328x; 1.1036x over previous
#include <cuda_runtime.h>
#include <cuda_bf16.h>
#include <cstdint>

// ---------------------------------------------------------------------------
// GroupedQueryAttention — Round 5: fused QKV GEMM (+rope+split epilogue),
// HMMA flash attention with bf16 epilogue, HMMA O-projection.
// ---------------------------------------------------------------------------

#define SEQ      2048
#define DIM      2048
#define KVDIM    512
#define NHEADS   32
#define NKV      8
#define GROUP    4
#define HDIM     64
#define GK       2048

// fp32 scratch (V only; needed for the transpose-split)
__device__ float g_V[SEQ * KVDIM];

// bf16 split scratch
__device__ __nv_bfloat16 g_xh[SEQ * DIM];
__device__ __nv_bfloat16 g_xl[SEQ * DIM];
__device__ __nv_bfloat16 g_Oh[SEQ * DIM];
__device__ __nv_bfloat16 g_Ol[SEQ * DIM];
__device__ __nv_bfloat16 g_wqhT[DIM * DIM];
__device__ __nv_bfloat16 g_wqlT[DIM * DIM];
__device__ __nv_bfloat16 g_wkhT[KVDIM * DIM];
__device__ __nv_bfloat16 g_wklT[KVDIM * DIM];
__device__ __nv_bfloat16 g_wvhT[KVDIM * DIM];
__device__ __nv_bfloat16 g_wvlT[KVDIM * DIM];
__device__ __nv_bfloat16 g_wohT[DIM * DIM];
__device__ __nv_bfloat16 g_wolT[DIM * DIM];

// attention operands (bf16 splits)
__device__ __nv_bfloat16 g_Qh[SEQ * DIM];     // pre-scaled by 0.125, rope applied
__device__ __nv_bfloat16 g_Ql[SEQ * DIM];
__device__ __nv_bfloat16 g_Kh[SEQ * KVDIM];   // rope applied
__device__ __nv_bfloat16 g_Kl[SEQ * KVDIM];
__device__ __nv_bfloat16 g_Vth[KVDIM * SEQ];  // V transposed: [512][2048]
__device__ __nv_bfloat16 g_Vtl[KVDIM * SEQ];

// ---------------------------------------------------------------------------
// PTX helpers (portable)
// ---------------------------------------------------------------------------
__device__ __forceinline__ uint32_t smem_u32(const void* p) {
    uint32_t a;
    asm("{ .reg .u64 t; cvta.to.shared.u64 t, %1; cvt.u32.u64 %0, t; }"
        : "=r"(a) : "l"(p));
    return a;
}

#define CP_ASYNC16(dst_u32, src_ptr) \
    asm volatile("cp.async.cg.shared.global [%0], [%1], 16;" \
                 :: "r"(dst_u32), "l"(src_ptr))
#define CP_COMMIT() asm volatile("cp.async.commit_group;" ::: "memory")
#define CP_WAIT2()  asm volatile("cp.async.wait_group 2;" ::: "memory")
#define CP_WAIT1()  asm volatile("cp.async.wait_group 1;" ::: "memory")
#define CP_WAIT0()  asm volatile("cp.async.wait_group 0;" ::: "memory")

__device__ __forceinline__ void ldsm_x4(uint32_t* r, uint32_t addr) {
    asm volatile("ldmatrix.sync.aligned.m8n8.x4.shared.b16 {%0,%1,%2,%3}, [%4];"
                 : "=r"(r[0]), "=r"(r[1]), "=r"(r[2]), "=r"(r[3]) : "r"(addr));
}

__device__ __forceinline__ void mma16816(float* c, const uint32_t* a,
                                         const uint32_t* b) {
    asm volatile(
        "mma.sync.aligned.m16n8k16.row.col.f32.bf16.bf16.f32 "
        "{%0,%1,%2,%3}, {%4,%5,%6,%7}, {%8,%9}, {%0,%1,%2,%3};"
        : "+f"(c[0]), "+f"(c[1]), "+f"(c[2]), "+f"(c[3])
        : "r"(a[0]), "r"(a[1]), "r"(a[2]), "r"(a[3]), "r"(b[0]), "r"(b[1]));
}

// split two fp32 into packed bf16x2 hi + lo
__device__ __forceinline__ void split2(float a, float b,
                                       uint32_t& hi, uint32_t& lo) {
    __nv_bfloat162 H = __floats2bfloat162_rn(a, b);
    float2 Hf = __bfloat1622float2(H);
    __nv_bfloat162 L = __floats2bfloat162_rn(a - Hf.x, b - Hf.y);
    hi = *reinterpret_cast<uint32_t*>(&H);
    lo = *reinterpret_cast<uint32_t*>(&L);
}

// ---------------------------------------------------------------------------
// GEMM tiling constants (shared by qkv_gemm and gemm3)
// ---------------------------------------------------------------------------
#define KCH      32
#define LDS_H    40
#define TILE_B   (128 * LDS_H * 2)
#define STAGE_B  (4 * TILE_B)
#define NSTAGE   3
#define GEMM_SMEM (NSTAGE * STAGE_B)

__device__ __forceinline__ void issue_stage(
    const __nv_bfloat16* __restrict__ Ah, const __nv_bfloat16* __restrict__ Al,
    const __nv_bfloat16* __restrict__ Bh, const __nv_bfloat16* __restrict__ Bl,
    int m0, int n0, int k0, uint32_t s_u32, int tid)
{
    const __nv_bfloat16* gp[4] = { Ah, Al, Bh, Bl };
    const int r0[4] = { m0, m0, n0, n0 };
    #pragma unroll
    for (int p = 0; p < 4; p++) {
        #pragma unroll
        for (int i = 0; i < 2; i++) {
            int e   = tid + i * 256;
            int row = e >> 2;
            int q   = e & 3;
            const __nv_bfloat16* src =
                gp[p] + (size_t)(r0[p] + row) * GK + k0 + q * 8;
            uint32_t dst = s_u32 + p * TILE_B + row * (LDS_H * 2) + q * 16;
            CP_ASYNC16(dst, src);
        }
    }
}

// mainloop body macro-free: computes acc[2][8][4] for one 128x128 tile
__device__ __forceinline__ void gemm_mainloop(
    const __nv_bfloat16* Ah, const __nv_bfloat16* Al,
    const __nv_bfloat16* Bh, const __nv_bfloat16* Bl,
    int m0, int n0, uint32_t sm0, int tid, int wm, int wn,
    int lrow, int lcol, float acc[2][8][4])
{
    const int NC = GK / KCH;

    issue_stage(Ah, Al, Bh, Bl, m0, n0, 0 * KCH, sm0, tid);
    CP_COMMIT();
    issue_stage(Ah, Al, Bh, Bl, m0, n0, 1 * KCH, sm0 + STAGE_B, tid);
    CP_COMMIT();

    for (int c = 0; c < NC; c++) {
        if (c + 2 < NC) {
            issue_stage(Ah, Al, Bh, Bl, m0, n0, (c + 2) * KCH,
                        sm0 + ((c + 2) % NSTAGE) * STAGE_B, tid);
            CP_COMMIT();
            CP_WAIT2();
        } else {
            CP_WAIT0();
        }
        __syncthreads();

        const uint32_t sb  = sm0 + (c % NSTAGE) * STAGE_B;
        const uint32_t sAh = sb + 0 * TILE_B;
        const uint32_t sAl = sb + 1 * TILE_B;
        const uint32_t sBh = sb + 2 * TILE_B;
        const uint32_t sBl = sb + 3 * TILE_B;

        #pragma unroll
        for (int kk = 0; kk < 2; kk++) {
            uint32_t ah[2][4], al[2][4], bh[8][2], bl[8][2];
            #pragma unroll
            for (int mt = 0; mt < 2; mt++) {
                uint32_t off =
                    (uint32_t)((wm * 32 + mt * 16 + lrow) * LDS_H + kk * 16 + lcol) * 2;
                ldsm_x4(ah[mt], sAh + off);
                ldsm_x4(al[mt], sAl + off);
            }
            #pragma unroll
            for (int nt = 0; nt < 4; nt++) {
                uint32_t off =
                    (uint32_t)((wn * 64 + nt * 16 + lrow) * LDS_H + kk * 16 + lcol) * 2;
                uint32_t t[4];
                ldsm_x4(t, sBh + off);
                bh[2 * nt][0]     = t[0]; bh[2 * nt][1]     = t[2];
                bh[2 * nt + 1][0] = t[1]; bh[2 * nt + 1][1] = t[3];
                ldsm_x4(t, sBl + off);
                bl[2 * nt][0]     = t[0]; bl[2 * nt][1]     = t[2];
                bl[2 * nt + 1][0] = t[1]; bl[2 * nt + 1][1] = t[3];
            }
            #pragma unroll
            for (int mt = 0; mt < 2; mt++)
                #pragma unroll
                for (int n8 = 0; n8 < 8; n8++) {
                    mma16816(acc[mt][n8], ah[mt], bh[n8]);
                    mma16816(acc[mt][n8], ah[mt], bl[n8]);
                    mma16816(acc[mt][n8], al[mt], bh[n8]);
                }
        }
        __syncthreads();
    }
}

// ---------------------------------------------------------------------------
// Fused QKV GEMM: grid (24, 16).
//   bx 0..15  : Q tile  -> rope, *0.125, split -> g_Qh/g_Ql   (ld 2048)
//   bx 16..19 : K tile  -> rope, split -> g_Kh/g_Kl           (ld 512)
//   bx 20..23 : V tile  -> fp32 -> g_V                        (ld 512)
// ---------------------------------------------------------------------------
#define LN10K_32 0.2878231366f   // ln(10000)/32

__global__ void __launch_bounds__(256, 1)
qkv_gemm_kernel(const __nv_bfloat16* __restrict__ xh,
                const __nv_bfloat16* __restrict__ xl,
                const __nv_bfloat16* __restrict__ wqh,
                const __nv_bfloat16* __restrict__ wql,
                const __nv_bfloat16* __restrict__ wkh,
                const __nv_bfloat16* __restrict__ wkl,
                const __nv_bfloat16* __restrict__ wvh,
                const __nv_bfloat16* __restrict__ wvl,
                __nv_bfloat16* __restrict__ Qh, __nv_bfloat16* __restrict__ Ql,
                __nv_bfloat16* __restrict__ Kh, __nv_bfloat16* __restrict__ Kl,
                float* __restrict__ V)
{
    extern __shared__ char smem[];
    const uint32_t sm0 = smem_u32(smem);
    const int tid  = threadIdx.x;
    const int wid  = tid >> 5;
    const int lane = tid & 31;
    const int wm   = wid & 3;
    const int wn   = wid >> 2;
    const int m0   = blockIdx.y * 128;
    const int bx   = blockIdx.x;

    int mode, n0;
    const __nv_bfloat16 *Bh, *Bl;
    if (bx < 16)      { mode = 0; n0 = bx * 128;        Bh = wqh; Bl = wql; }
    else if (bx < 20) { mode = 1; n0 = (bx - 16) * 128; Bh = wkh; Bl = wkl; }
    else              { mode = 2; n0 = (bx - 20) * 128; Bh = wvh; Bl = wvl; }

    const int lrow = (lane & 7) + ((lane >> 3) & 1) * 8;
    const int lcol = (lane >> 4) * 8;

    float acc[2][8][4];
    #pragma unroll
    for (int mt = 0; mt < 2; mt++)
        #pragma unroll
        for (int n8 = 0; n8 < 8; n8++)
            #pragma unroll
            for (int j = 0; j < 4; j++) acc[mt][n8][j] = 0.f;

    gemm_mainloop(xh, xl, Bh, Bl, m0, n0, sm0, tid, wm, wn, lrow, lcol, acc);

    const int cr = lane >> 2;
    const int cc = (lane & 3) * 2;

    if (mode == 2) {
        // V: plain fp32 store
        #pragma unroll
        for (int mt = 0; mt < 2; mt++)
            #pragma unroll
            for (int n8 = 0; n8 < 8; n8++) {
                float* base = V + (size_t)(m0 + wm * 32 + mt * 16 + cr) * KVDIM
                                + n0 + wn * 64 + n8 * 8 + cc;
                *reinterpret_cast<float2*>(base) =
                    make_float2(acc[mt][n8][0], acc[mt][n8][1]);
                *reinterpret_cast<float2*>(base + 8 * (size_t)KVDIM) =
                    make_float2(acc[mt][n8][2], acc[mt][n8][3]);
            }
        return;
    }

    // Q/K: rope + split epilogue. Warp tile is head-aligned (64 cols).
    const float scale = (mode == 0) ? 0.125f : 1.0f;
    const int   ldo   = (mode == 0) ? DIM : KVDIM;
    __nv_bfloat16* OH = (mode == 0) ? Qh : Kh;
    __nv_bfloat16* OL = (mode == 0) ? Ql : Kl;

    #pragma unroll
    for (int mt = 0; mt < 2; mt++) {
        const int r0 = m0 + wm * 32 + mt * 16 + cr;
        #pragma unroll
        for (int n8 = 0; n8 < 4; n8++) {
            const int d0 = n8 * 8 + cc;                    // 0..30
            const float f0 = __expf(-(float)d0 * LN10K_32);
            const float f1 = __expf(-(float)(d0 + 1) * LN10K_32);
            #pragma unroll
            for (int half = 0; half < 2; half++) {
                const int r = r0 + half * 8;
                float c0, s0, c1, s1;
                sincosf((float)r * f0, &s0, &c0);
                sincosf((float)r * f1, &s1, &c1);
                const float x1a = acc[mt][n8][half * 2 + 0];
                const float x1b = acc[mt][n8][half * 2 + 1];
                const float x2a = acc[mt][n8 + 4][half * 2 + 0];
                const float x2b = acc[mt][n8 + 4][half * 2 + 1];
                const float lo0 = (x1a * c0 - x2a * s0) * scale;
                const float lo1 = (x1b * c1 - x2b * s1) * scale;
                const float hi0 = (x2a * c0 + x1a * s0) * scale;
                const float hi1 = (x2b * c1 + x1b * s1) * scale;
                const size_t off = (size_t)r * ldo + n0 + wn * 64 + n8 * 8 + cc;
                uint32_t H, L;
                split2(lo0, lo1, H, L);
                *reinterpret_cast<uint32_t*>(OH + off) = H;
                *reinterpret_cast<uint32_t*>(OL + off) = L;
                split2(hi0, hi1, H, L);
                *reinterpret_cast<uint32_t*>(OH + off + 32) = H;
                *reinterpret_cast<uint32_t*>(OL + off + 32) = L;
            }
        }
    }
}

// ---------------------------------------------------------------------------
// O-projection GEMM (fp32 out)
// ---------------------------------------------------------------------------
__global__ void __launch_bounds__(256, 1)
gemm3_kernel(const __nv_bfloat16* __restrict__ Ah,
             const __nv_bfloat16* __restrict__ Al,
             const __nv_bfloat16* __restrict__ BhT,
             const __nv_bfloat16* __restrict__ BlT,
             float* __restrict__ C, int ldc)
{
    extern __shared__ char smem[];
    const uint32_t sm0 = smem_u32(smem);
    const int tid  = threadIdx.x;
    const int wid  = tid >> 5;
    const int lane = tid & 31;
    const int wm   = wid & 3;
    const int wn   = wid >> 2;
    const int m0   = blockIdx.y * 128;
    const int n0   = blockIdx.x * 128;

    const int lrow = (lane & 7) + ((lane >> 3) & 1) * 8;
    const int lcol = (lane >> 4) * 8;

    float acc[2][8][4];
    #pragma unroll
    for (int mt = 0; mt < 2; mt++)
        #pragma unroll
        for (int n8 = 0; n8 < 8; n8++)
            #pragma unroll
            for (int j = 0; j < 4; j++) acc[mt][n8][j] = 0.f;

    gemm_mainloop(Ah, Al, BhT, BlT, m0, n0, sm0, tid, wm, wn, lrow, lcol, acc);

    const int cr = lane >> 2;
    const int cc = (lane & 3) * 2;
    #pragma unroll
    for (int mt = 0; mt < 2; mt++) {
        #pragma unroll
        for (int n8 = 0; n8 < 8; n8++) {
            float* base = C + (size_t)(m0 + wm * 32 + mt * 16 + cr) * ldc
                            + n0 + wn * 64 + n8 * 8 + cc;
            *reinterpret_cast<float2*>(base) =
                make_float2(acc[mt][n8][0], acc[mt][n8][1]);
            *reinterpret_cast<float2*>(base + 8 * (size_t)ldc) =
                make_float2(acc[mt][n8][2], acc[mt][n8][3]);
        }
    }
}

// ---------------------------------------------------------------------------
// Split fp32 -> bf16 hi/lo
// ---------------------------------------------------------------------------
__global__ void split_kernel(const float* __restrict__ in,
                             __nv_bfloat16* __restrict__ hi,
                             __nv_bfloat16* __restrict__ lo)
{
    int i = (blockIdx.x * 256 + threadIdx.x) * 4;
    float4 v = *reinterpret_cast<const float4*>(in + i);
    float vv[4] = { v.x, v.y, v.z, v.w };
    __nv_bfloat16 h[4], l[4];
    #pragma unroll
    for (int j = 0; j < 4; j++) {
        h[j] = __float2bfloat16(vv[j]);
        l[j] = __float2bfloat16(vv[j] - __bfloat162float(h[j]));
    }
    *reinterpret_cast<uint2*>(hi + i) = *reinterpret_cast<uint2*>(h);
    *reinterpret_cast<uint2*>(lo + i) = *reinterpret_cast<uint2*>(l);
}

// ---------------------------------------------------------------------------
// Transpose + split weights: w[K,N] fp32 -> hiT/loT [N,K] bf16
// ---------------------------------------------------------------------------
__global__ void tsplit_kernel(const float* __restrict__ w,
                              __nv_bfloat16* __restrict__ hiT,
                              __nv_bfloat16* __restrict__ loT,
                              int K, int N)
{
    __shared__ float t[32][33];
    const int k0 = blockIdx.y * 32;
    const int n0 = blockIdx.x * 32;
    const int tx = threadIdx.x, ty = threadIdx.y;
    #pragma unroll
    for (int r = 0; r < 4; r++)
        t[ty + 8 * r][tx] = w[(size_t)(k0 + ty + 8 * r) * N + n0 + tx];
    __syncthreads();
    #pragma unroll
    for (int r = 0; r < 4; r++) {
        int row = ty + 8 * r;
        float v = t[tx][row];
        __nv_bfloat16 h = __float2bfloat16(v);
        __nv_bfloat16 l = __float2bfloat16(v - __bfloat162float(h));
        size_t o = (size_t)(n0 + row) * K + k0 + tx;
        hiT[o] = h;
        loT[o] = l;
    }
}

// ---------------------------------------------------------------------------
// Transpose + split V: V[2048,512] fp32 -> Vt hi/lo [512][2048] bf16
// ---------------------------------------------------------------------------
__global__ void vtsplit_kernel(const float* __restrict__ V,
                               __nv_bfloat16* __restrict__ Vth,
                               __nv_bfloat16* __restrict__ Vtl)
{
    __shared__ float t[32][33];
    const int sB = blockIdx.x * 32;
    const int dB = blockIdx.y * 32;
    const int tx = threadIdx.x, ty = threadIdx.y;
    #pragma unroll
    for (int r = 0; r < 4; r++)
        t[ty + 8 * r][tx] = V[(size_t)(sB + ty + 8 * r) * KVDIM + dB + tx];
    __syncthreads();
    #pragma unroll
    for (int r = 0; r < 4; r++) {
        int dd = ty + 8 * r;
        float v = t[tx][dd];
        __nv_bfloat16 h = __float2bfloat16(v);
        __nv_bfloat16 l = __float2bfloat16(v - __bfloat162float(h));
        size_t o = (size_t)(dB + dd) * SEQ + sB + tx;
        Vth[o] = h;
        Vtl[o] = l;
    }
}

// ---------------------------------------------------------------------------
// HMMA flash attention; epilogue writes bf16 hi/lo directly.
// ---------------------------------------------------------------------------
#define BQ     64
#define BK     64
#define PADH   72
#define ROWB   (PADH * 2)
#define ATILE  (64 * ROWB)
#define ASTAGE (4 * ATILE)
#define SM_QH  0
#define SM_QL  ATILE
#define SM_KV  (2 * ATILE)
#define ATT_SMEM (SM_KV + 2 * ASTAGE)

__device__ __forceinline__ void att_issue(
    uint32_t sb,
    const __nv_bfloat16* __restrict__ Kh, const __nv_bfloat16* __restrict__ Kl,
    const __nv_bfloat16* __restrict__ Vth, const __nv_bfloat16* __restrict__ Vtl,
    int k0, int kh, int tid)
{
    const size_t kbase  = (size_t)kh * HDIM;
    const size_t vtbase = (size_t)kh * HDIM * SEQ;
    #pragma unroll
    for (int i = 0; i < 4; i++) {
        int idx = tid + i * 128;
        int r = idx >> 3, q = idx & 7;
        uint32_t so = (uint32_t)(r * ROWB + q * 16);
        CP_ASYNC16(sb + 0 * ATILE + so,
                   Kh + (size_t)(k0 + r) * KVDIM + kbase + q * 8);
        CP_ASYNC16(sb + 1 * ATILE + so,
                   Kl + (size_t)(k0 + r) * KVDIM + kbase + q * 8);
        CP_ASYNC16(sb + 2 * ATILE + so,
                   Vth + vtbase + (size_t)r * SEQ + k0 + q * 8);
        CP_ASYNC16(sb + 3 * ATILE + so,
                   Vtl + vtbase + (size_t)r * SEQ + k0 + q * 8);
    }
}

__global__ void __launch_bounds__(128)
attn_mma_kernel(const __nv_bfloat16* __restrict__ Qh,
                const __nv_bfloat16* __restrict__ Ql,
                const __nv_bfloat16* __restrict__ Kh,
                const __nv_bfloat16* __restrict__ Kl,
                const __nv_bfloat16* __restrict__ Vth,
                const __nv_bfloat16* __restrict__ Vtl,
                __nv_bfloat16* __restrict__ Ohi,
                __nv_bfloat16* __restrict__ Olo)
{
    extern __shared__ char smem[];
    const uint32_t s0 = smem_u32(smem);
    const int tid = threadIdx.x, wid = tid >> 5, lane = tid & 31;
    const int h  = blockIdx.y;
    const int kh = h / GROUP;
    const int q0 = blockIdx.x * BQ;
    const int lrow = (lane & 7) + ((lane >> 3) & 1) * 8;
    const int lcol = (lane >> 4) * 8;
    const int gr = lane >> 2, tg = lane & 3;
    const int NT = SEQ / BK;

    #pragma unroll
    for (int i = 0; i < 4; i++) {
        int idx = tid + i * 128;
        int r = idx >> 3, q = idx & 7;
        uint32_t so = (uint32_t)(r * ROWB + q * 16);
        CP_ASYNC16(s0 + SM_QH + so,
                   Qh + (size_t)(q0 + r) * DIM + h * HDIM + q * 8);
        CP_ASYNC16(s0 + SM_QL + so,
                   Ql + (size_t)(q0 + r) * DIM + h * HDIM + q * 8);
    }
    att_issue(s0 + SM_KV, Kh, Kl, Vth, Vtl, 0, kh, tid);
    CP_COMMIT();
    CP_WAIT0();
    __syncthreads();

    uint32_t qfh[4][4], qfl[4][4];
    #pragma unroll
    for (int kc = 0; kc < 4; kc++) {
        uint32_t off = (uint32_t)((wid * 16 + lrow) * ROWB + (kc * 16 + lcol) * 2);
        ldsm_x4(qfh[kc], s0 + SM_QH + off);
        ldsm_x4(qfl[kc], s0 + SM_QL + off);
    }

    float acc[8][4];
    #pragma unroll
    for (int j = 0; j < 8; j++)
        #pragma unroll
        for (int i = 0; i < 4; i++) acc[j][i] = 0.f;
    float m0 = -1e30f, m1 = -1e30f, l0 = 0.f, l1 = 0.f;

    for (int c = 0; c < NT; c++) {
        if (c + 1 < NT) {
            att_issue(s0 + SM_KV + ((c + 1) & 1) * ASTAGE,
                      Kh, Kl, Vth, Vtl, (c + 1) * BK, kh, tid);
            CP_COMMIT();
            CP_WAIT1();
        } else {
            CP_WAIT0();
        }
        __syncthreads();

        const uint32_t sb  = s0 + SM_KV + (c & 1) * ASTAGE;
        const uint32_t sKh = sb + 0 * ATILE;
        const uint32_t sKl = sb + 1 * ATILE;
        const uint32_t sVh = sb + 2 * ATILE;
        const uint32_t sVl = sb + 3 * ATILE;

        float s[8][4];
        #pragma unroll
        for (int j = 0; j < 8; j++)
            #pragma unroll
            for (int i = 0; i < 4; i++) s[j][i] = 0.f;

        #pragma unroll
        for (int kc = 0; kc < 4; kc++) {
            #pragma unroll
            for (int nt = 0; nt < 4; nt++) {
                uint32_t off = (uint32_t)((nt * 16 + lrow) * ROWB + (kc * 16 + lcol) * 2);
                uint32_t th[4], tl[4];
                ldsm_x4(th, sKh + off);
                ldsm_x4(tl, sKl + off);
                uint32_t b0h[2] = { th[0], th[2] }, b1h[2] = { th[1], th[3] };
                uint32_t b0l[2] = { tl[0], tl[2] }, b1l[2] = { tl[1], tl[3] };
                mma16816(s[2 * nt],     qfh[kc], b0h);
                mma16816(s[2 * nt],     qfh[kc], b0l);
                mma16816(s[2 * nt],     qfl[kc], b0h);
                mma16816(s[2 * nt + 1], qfh[kc], b1h);
                mma16816(s[2 * nt + 1], qfh[kc], b1l);
                mma16816(s[2 * nt + 1], qfl[kc], b1h);
            }
        }

        float tm0 = -1e30f, tm1 = -1e30f;
        #pragma unroll
        for (int j = 0; j < 8; j++) {
            tm0 = fmaxf(tm0, fmaxf(s[j][0], s[j][1]));
            tm1 = fmaxf(tm1, fmaxf(s[j][2], s[j][3]));
        }
        tm0 = fmaxf(tm0, __shfl_xor_sync(0xffffffffu, tm0, 1));
        tm0 = fmaxf(tm0, __shfl_xor_sync(0xffffffffu, tm0, 2));
        tm1 = fmaxf(tm1, __shfl_xor_sync(0xffffffffu, tm1, 1));
        tm1 = fmaxf(tm1, __shfl_xor_sync(0xffffffffu, tm1, 2));

        float nm0 = fmaxf(m0, tm0), nm1 = fmaxf(m1, tm1);
        float corr0 = __expf(m0 - nm0), corr1 = __expf(m1 - nm1);
        m0 = nm0; m1 = nm1;

        float sum0 = 0.f, sum1 = 0.f;
        #pragma unroll
        for (int j = 0; j < 8; j++) {
            s[j][0] = __expf(s[j][0] - m0);
            s[j][1] = __expf(s[j][1] - m0);
            s[j][2] = __expf(s[j][2] - m1);
            s[j][3] = __expf(s[j][3] - m1);
            sum0 += s[j][0] + s[j][1];
            sum1 += s[j][2] + s[j][3];
        }
        sum0 += __shfl_xor_sync(0xffffffffu, sum0, 1);
        sum0 += __shfl_xor_sync(0xffffffffu, sum0, 2);
        sum1 += __shfl_xor_sync(0xffffffffu, sum1, 1);
        sum1 += __shfl_xor_sync(0xffffffffu, sum1, 2);
        l0 = l0 * corr0 + sum0;
        l1 = l1 * corr1 + sum1;

        #pragma unroll
        for (int j = 0; j < 8; j++) {
            acc[j][0] *= corr0; acc[j][1] *= corr0;
            acc[j][2] *= corr1; acc[j][3] *= corr1;
        }

        #pragma unroll
        for (int kc = 0; kc < 4; kc++) {
            uint32_t aph[4], apl[4];
            split2(s[2 * kc][0],     s[2 * kc][1],     aph[0], apl[0]);
            split2(s[2 * kc][2],     s[2 * kc][3],     aph[1], apl[1]);
            split2(s[2 * kc + 1][0], s[2 * kc + 1][1], aph[2], apl[2]);
            split2(s[2 * kc + 1][2], s[2 * kc + 1][3], aph[3], apl[3]);
            #pragma unroll
            for (int nt = 0; nt < 4; nt++) {
                uint32_t off = (uint32_t)((nt * 16 + lrow) * ROWB + (kc * 16 + lcol) * 2);
                uint32_t th[4], tl[4];
                ldsm_x4(th, sVh + off);
                ldsm_x4(tl, sVl + off);
                uint32_t b0h[2] = { th[0], th[2] }, b1h[2] = { th[1], th[3] };
                uint32_t b0l[2] = { tl[0], tl[2] }, b1l[2] = { tl[1], tl[3] };
                mma16816(acc[2 * nt],     aph, b0h);
                mma16816(acc[2 * nt],     aph, b0l);
                mma16816(acc[2 * nt],     apl, b0h);
                mma16816(acc[2 * nt + 1], aph, b1h);
                mma16816(acc[2 * nt + 1], aph, b1l);
                mma16816(acc[2 * nt + 1], apl, b1h);
            }
        }
        __syncthreads();
    }

    // epilogue: normalize + split to bf16 hi/lo
    const float inv0 = 1.f / l0, inv1 = 1.f / l1;
    #pragma unroll
    for (int j = 0; j < 8; j++) {
        const size_t off0 = (size_t)(q0 + wid * 16 + gr) * DIM + h * HDIM + j * 8 + tg * 2;
        const size_t off1 = off0 + 8 * (size_t)DIM;
        uint32_t H, L;
        split2(acc[j][0] * inv0, acc[j][1] * inv0, H, L);
        *reinterpret_cast<uint32_t*>(Ohi + off0) = H;
        *reinterpret_cast<uint32_t*>(Olo + off0) = L;
        split2(acc[j][2] * inv1, acc[j][3] * inv1, H, L);
        *reinterpret_cast<uint32_t*>(Ohi + off1) = H;
        *reinterpret_cast<uint32_t*>(Olo + off1) = L;
    }
}

// ---------------------------------------------------------------------------
// Launch
// ---------------------------------------------------------------------------
extern "C" void kernel_launch(void* const* d_in, const int* in_sizes, int n_in,
                              void* d_out, int out_size)
{
    const float* x  = (const float*)d_in[0];
    const float* wq = (const float*)d_in[1];
    const float* wk = (const float*)d_in[2];
    const float* wv = (const float*)d_in[3];
    const float* wo = (const float*)d_in[4];
    float* out = (float*)d_out;

    float* Vb;
    cudaGetSymbolAddress((void**)&Vb, g_V);

    __nv_bfloat16 *xh, *xl, *Oh, *Ol;
    __nv_bfloat16 *wqh, *wql, *wkh, *wkl, *wvh, *wvl, *woh, *wol;
    __nv_bfloat16 *qsh, *qsl, *ksh, *ksl, *vth, *vtl;
    cudaGetSymbolAddress((void**)&xh, g_xh);
    cudaGetSymbolAddress((void**)&xl, g_xl);
    cudaGetSymbolAddress((void**)&Oh, g_Oh);
    cudaGetSymbolAddress((void**)&Ol, g_Ol);
    cudaGetSymbolAddress((void**)&wqh, g_wqhT);
    cudaGetSymbolAddress((void**)&wql, g_wqlT);
    cudaGetSymbolAddress((void**)&wkh, g_wkhT);
    cudaGetSymbolAddress((void**)&wkl, g_wklT);
    cudaGetSymbolAddress((void**)&wvh, g_wvhT);
    cudaGetSymbolAddress((void**)&wvl, g_wvlT);
    cudaGetSymbolAddress((void**)&woh, g_wohT);
    cudaGetSymbolAddress((void**)&wol, g_wolT);
    cudaGetSymbolAddress((void**)&qsh, g_Qh);
    cudaGetSymbolAddress((void**)&qsl, g_Ql);
    cudaGetSymbolAddress((void**)&ksh, g_Kh);
    cudaGetSymbolAddress((void**)&ksl, g_Kl);
    cudaGetSymbolAddress((void**)&vth, g_Vth);
    cudaGetSymbolAddress((void**)&vtl, g_Vtl);

    cudaFuncSetAttribute(qkv_gemm_kernel,
        cudaFuncAttributeMaxDynamicSharedMemorySize, GEMM_SMEM);
    cudaFuncSetAttribute(gemm3_kernel,
        cudaFuncAttributeMaxDynamicSharedMemorySize, GEMM_SMEM);
    cudaFuncSetAttribute(attn_mma_kernel,
        cudaFuncAttributeMaxDynamicSharedMemorySize, ATT_SMEM);

    // input splits
    split_kernel<<<SEQ * DIM / 1024, 256>>>(x, xh, xl);
    tsplit_kernel<<<dim3(DIM / 32, DIM / 32), dim3(32, 8)>>>(wq, wqh, wql, DIM, DIM);
    tsplit_kernel<<<dim3(KVDIM / 32, DIM / 32), dim3(32, 8)>>>(wk, wkh, wkl, DIM, KVDIM);
    tsplit_kernel<<<dim3(KVDIM / 32, DIM / 32), dim3(32, 8)>>>(wv, wvh, wvl, DIM, KVDIM);
    tsplit_kernel<<<dim3(DIM / 32, DIM / 32), dim3(32, 8)>>>(wo, woh, wol, DIM, DIM);

    // fused QKV projection (+rope +split epilogues)
    qkv_gemm_kernel<<<dim3(24, 16), 256, GEMM_SMEM>>>(
        xh, xl, wqh, wql, wkh, wkl, wvh, wvl,
        qsh, qsl, ksh, ksl, Vb);

    // V transpose-split
    vtsplit_kernel<<<dim3(SEQ / 32, KVDIM / 32), dim3(32, 8)>>>(Vb, vth, vtl);

    // HMMA flash attention -> bf16 hi/lo
    attn_mma_kernel<<<dim3(SEQ / BQ, NHEADS), 128, ATT_SMEM>>>(
        qsh, qsl, ksh, ksl, vth, vtl, Oh, Ol);

    // output projection
    gemm3_kernel<<<dim3(DIM / 128, SEQ / 128), 256, GEMM_SMEM>>>(
        Oh, Ol, woh, wol, out, DIM);
}

// round 6
// speedup vs baseline: 3.3554x; 1.1441x over previous
#include <cuda_runtime.h>
#include <cuda_bf16.h>
#include <cstdint>

// ---------------------------------------------------------------------------
// GroupedQueryAttention — Round 6: 2-CTA/SM GEMMs (2-stage, low-reg loop),
// 2-head-sharing HMMA flash attention, merged weight splits.
// ---------------------------------------------------------------------------

#define SEQ      2048
#define DIM      2048
#define KVDIM    512
#define NHEADS   32
#define NKV      8
#define GROUP    4
#define HDIM     64
#define GK       2048

// fp32 scratch (V only)
__device__ float g_V[SEQ * KVDIM];

// bf16 split scratch
__device__ __nv_bfloat16 g_xh[SEQ * DIM];
__device__ __nv_bfloat16 g_xl[SEQ * DIM];
__device__ __nv_bfloat16 g_Oh[SEQ * DIM];
__device__ __nv_bfloat16 g_Ol[SEQ * DIM];
__device__ __nv_bfloat16 g_wqhT[DIM * DIM];
__device__ __nv_bfloat16 g_wqlT[DIM * DIM];
__device__ __nv_bfloat16 g_wkhT[KVDIM * DIM];
__device__ __nv_bfloat16 g_wklT[KVDIM * DIM];
__device__ __nv_bfloat16 g_wvhT[KVDIM * DIM];
__device__ __nv_bfloat16 g_wvlT[KVDIM * DIM];
__device__ __nv_bfloat16 g_wohT[DIM * DIM];
__device__ __nv_bfloat16 g_wolT[DIM * DIM];

// attention operands
__device__ __nv_bfloat16 g_Qh[SEQ * DIM];     // rope applied, *0.125
__device__ __nv_bfloat16 g_Ql[SEQ * DIM];
__device__ __nv_bfloat16 g_Kh[SEQ * KVDIM];   // rope applied
__device__ __nv_bfloat16 g_Kl[SEQ * KVDIM];
__device__ __nv_bfloat16 g_Vth[KVDIM * SEQ];  // V transposed [512][2048]
__device__ __nv_bfloat16 g_Vtl[KVDIM * SEQ];

// ---------------------------------------------------------------------------
// PTX helpers
// ---------------------------------------------------------------------------
__device__ __forceinline__ uint32_t smem_u32(const void* p) {
    uint32_t a;
    asm("{ .reg .u64 t; cvta.to.shared.u64 t, %1; cvt.u32.u64 %0, t; }"
        : "=r"(a) : "l"(p));
    return a;
}

#define CP_ASYNC16(dst_u32, src_ptr) \
    asm volatile("cp.async.cg.shared.global [%0], [%1], 16;" \
                 :: "r"(dst_u32), "l"(src_ptr))
#define CP_COMMIT() asm volatile("cp.async.commit_group;" ::: "memory")
#define CP_WAIT1()  asm volatile("cp.async.wait_group 1;" ::: "memory")
#define CP_WAIT0()  asm volatile("cp.async.wait_group 0;" ::: "memory")

__device__ __forceinline__ void ldsm_x4(uint32_t* r, uint32_t addr) {
    asm volatile("ldmatrix.sync.aligned.m8n8.x4.shared.b16 {%0,%1,%2,%3}, [%4];"
                 : "=r"(r[0]), "=r"(r[1]), "=r"(r[2]), "=r"(r[3]) : "r"(addr));
}

__device__ __forceinline__ void mma16816(float* c, const uint32_t* a,
                                         const uint32_t* b) {
    asm volatile(
        "mma.sync.aligned.m16n8k16.row.col.f32.bf16.bf16.f32 "
        "{%0,%1,%2,%3}, {%4,%5,%6,%7}, {%8,%9}, {%0,%1,%2,%3};"
        : "+f"(c[0]), "+f"(c[1]), "+f"(c[2]), "+f"(c[3])
        : "r"(a[0]), "r"(a[1]), "r"(a[2]), "r"(a[3]), "r"(b[0]), "r"(b[1]));
}

__device__ __forceinline__ void split2(float a, float b,
                                       uint32_t& hi, uint32_t& lo) {
    __nv_bfloat162 H = __floats2bfloat162_rn(a, b);
    float2 Hf = __bfloat1622float2(H);
    __nv_bfloat162 L = __floats2bfloat162_rn(a - Hf.x, b - Hf.y);
    hi = *reinterpret_cast<uint32_t*>(&H);
    lo = *reinterpret_cast<uint32_t*>(&L);
}

// ---------------------------------------------------------------------------
// GEMM tiling: 128x128 CTA tile, KCH=32, 2-stage cp.async, 2 CTAs/SM.
// ---------------------------------------------------------------------------
#define KCH      32
#define LDS_H    40
#define TILE_B   (128 * LDS_H * 2)
#define STAGE_B  (4 * TILE_B)          // 40960
#define GEMM_SMEM (2 * STAGE_B)        // 81920

__device__ __forceinline__ void issue_stage(
    const __nv_bfloat16* __restrict__ Ah, const __nv_bfloat16* __restrict__ Al,
    const __nv_bfloat16* __restrict__ Bh, const __nv_bfloat16* __restrict__ Bl,
    int m0, int n0, int k0, uint32_t s_u32, int tid)
{
    const __nv_bfloat16* gp[4] = { Ah, Al, Bh, Bl };
    const int r0[4] = { m0, m0, n0, n0 };
    #pragma unroll
    for (int p = 0; p < 4; p++) {
        #pragma unroll
        for (int i = 0; i < 2; i++) {
            int e   = tid + i * 256;
            int row = e >> 2;
            int q   = e & 3;
            const __nv_bfloat16* src =
                gp[p] + (size_t)(r0[p] + row) * GK + k0 + q * 8;
            uint32_t dst = s_u32 + p * TILE_B + row * (LDS_H * 2) + q * 16;
            CP_ASYNC16(dst, src);
        }
    }
}

__device__ __forceinline__ void gemm_mainloop(
    const __nv_bfloat16* Ah, const __nv_bfloat16* Al,
    const __nv_bfloat16* Bh, const __nv_bfloat16* Bl,
    int m0, int n0, uint32_t sm0, int tid, int wm, int wn,
    int lrow, int lcol, float acc[2][8][4])
{
    const int NC = GK / KCH;

    issue_stage(Ah, Al, Bh, Bl, m0, n0, 0, sm0, tid);
    CP_COMMIT();

    for (int c = 0; c < NC; c++) {
        if (c + 1 < NC) {
            issue_stage(Ah, Al, Bh, Bl, m0, n0, (c + 1) * KCH,
                        sm0 + ((c + 1) & 1) * STAGE_B, tid);
            CP_COMMIT();
            CP_WAIT1();
        } else {
            CP_WAIT0();
        }
        __syncthreads();

        const uint32_t sb  = sm0 + (c & 1) * STAGE_B;
        const uint32_t sAh = sb + 0 * TILE_B;
        const uint32_t sAl = sb + 1 * TILE_B;
        const uint32_t sBh = sb + 2 * TILE_B;
        const uint32_t sBl = sb + 3 * TILE_B;

        #pragma unroll
        for (int kk = 0; kk < 2; kk++) {
            uint32_t ah[2][4], al[2][4];
            #pragma unroll
            for (int mt = 0; mt < 2; mt++) {
                uint32_t off =
                    (uint32_t)((wm * 32 + mt * 16 + lrow) * LDS_H + kk * 16 + lcol) * 2;
                ldsm_x4(ah[mt], sAh + off);
                ldsm_x4(al[mt], sAl + off);
            }
            #pragma unroll
            for (int nt = 0; nt < 4; nt++) {
                uint32_t off =
                    (uint32_t)((wn * 64 + nt * 16 + lrow) * LDS_H + kk * 16 + lcol) * 2;
                uint32_t th[4], tl[4];
                ldsm_x4(th, sBh + off);
                ldsm_x4(tl, sBl + off);
                uint32_t b0h[2] = { th[0], th[2] }, b1h[2] = { th[1], th[3] };
                uint32_t b0l[2] = { tl[0], tl[2] }, b1l[2] = { tl[1], tl[3] };
                #pragma unroll
                for (int mt = 0; mt < 2; mt++) {
                    mma16816(acc[mt][2 * nt],     ah[mt], b0h);
                    mma16816(acc[mt][2 * nt],     ah[mt], b0l);
                    mma16816(acc[mt][2 * nt],     al[mt], b0h);
                    mma16816(acc[mt][2 * nt + 1], ah[mt], b1h);
                    mma16816(acc[mt][2 * nt + 1], ah[mt], b1l);
                    mma16816(acc[mt][2 * nt + 1], al[mt], b1h);
                }
            }
        }
        __syncthreads();
    }
}

// ---------------------------------------------------------------------------
// Fused QKV GEMM (+rope+split epilogues)
// ---------------------------------------------------------------------------
#define LN10K_32 0.2878231366f

__global__ void __launch_bounds__(256, 2)
qkv_gemm_kernel(const __nv_bfloat16* __restrict__ xh,
                const __nv_bfloat16* __restrict__ xl,
                const __nv_bfloat16* __restrict__ wqh,
                const __nv_bfloat16* __restrict__ wql,
                const __nv_bfloat16* __restrict__ wkh,
                const __nv_bfloat16* __restrict__ wkl,
                const __nv_bfloat16* __restrict__ wvh,
                const __nv_bfloat16* __restrict__ wvl,
                __nv_bfloat16* __restrict__ Qh, __nv_bfloat16* __restrict__ Ql,
                __nv_bfloat16* __restrict__ Kh, __nv_bfloat16* __restrict__ Kl,
                float* __restrict__ V)
{
    extern __shared__ char smem[];
    const uint32_t sm0 = smem_u32(smem);
    const int tid  = threadIdx.x;
    const int wid  = tid >> 5;
    const int lane = tid & 31;
    const int wm   = wid & 3;
    const int wn   = wid >> 2;
    const int m0   = blockIdx.y * 128;
    const int bx   = blockIdx.x;

    int mode, n0;
    const __nv_bfloat16 *Bh, *Bl;
    if (bx < 16)      { mode = 0; n0 = bx * 128;        Bh = wqh; Bl = wql; }
    else if (bx < 20) { mode = 1; n0 = (bx - 16) * 128; Bh = wkh; Bl = wkl; }
    else              { mode = 2; n0 = (bx - 20) * 128; Bh = wvh; Bl = wvl; }

    const int lrow = (lane & 7) + ((lane >> 3) & 1) * 8;
    const int lcol = (lane >> 4) * 8;

    float acc[2][8][4];
    #pragma unroll
    for (int mt = 0; mt < 2; mt++)
        #pragma unroll
        for (int n8 = 0; n8 < 8; n8++)
            #pragma unroll
            for (int j = 0; j < 4; j++) acc[mt][n8][j] = 0.f;

    gemm_mainloop(xh, xl, Bh, Bl, m0, n0, sm0, tid, wm, wn, lrow, lcol, acc);

    const int cr = lane >> 2;
    const int cc = (lane & 3) * 2;

    if (mode == 2) {
        #pragma unroll
        for (int mt = 0; mt < 2; mt++)
            #pragma unroll
            for (int n8 = 0; n8 < 8; n8++) {
                float* base = V + (size_t)(m0 + wm * 32 + mt * 16 + cr) * KVDIM
                                + n0 + wn * 64 + n8 * 8 + cc;
                *reinterpret_cast<float2*>(base) =
                    make_float2(acc[mt][n8][0], acc[mt][n8][1]);
                *reinterpret_cast<float2*>(base + 8 * (size_t)KVDIM) =
                    make_float2(acc[mt][n8][2], acc[mt][n8][3]);
            }
        return;
    }

    const float scale = (mode == 0) ? 0.125f : 1.0f;
    const int   ldo   = (mode == 0) ? DIM : KVDIM;
    __nv_bfloat16* OH = (mode == 0) ? Qh : Kh;
    __nv_bfloat16* OL = (mode == 0) ? Ql : Kl;

    #pragma unroll
    for (int mt = 0; mt < 2; mt++) {
        const int r0 = m0 + wm * 32 + mt * 16 + cr;
        #pragma unroll
        for (int n8 = 0; n8 < 4; n8++) {
            const int d0 = n8 * 8 + cc;
            const float f0 = __expf(-(float)d0 * LN10K_32);
            const float f1 = __expf(-(float)(d0 + 1) * LN10K_32);
            #pragma unroll
            for (int half = 0; half < 2; half++) {
                const int r = r0 + half * 8;
                float c0, s0, c1, s1;
                sincosf((float)r * f0, &s0, &c0);
                sincosf((float)r * f1, &s1, &c1);
                const float x1a = acc[mt][n8][half * 2 + 0];
                const float x1b = acc[mt][n8][half * 2 + 1];
                const float x2a = acc[mt][n8 + 4][half * 2 + 0];
                const float x2b = acc[mt][n8 + 4][half * 2 + 1];
                const float lo0 = (x1a * c0 - x2a * s0) * scale;
                const float lo1 = (x1b * c1 - x2b * s1) * scale;
                const float hi0 = (x2a * c0 + x1a * s0) * scale;
                const float hi1 = (x2b * c1 + x1b * s1) * scale;
                const size_t off = (size_t)r * ldo + n0 + wn * 64 + n8 * 8 + cc;
                uint32_t H, L;
                split2(lo0, lo1, H, L);
                *reinterpret_cast<uint32_t*>(OH + off) = H;
                *reinterpret_cast<uint32_t*>(OL + off) = L;
                split2(hi0, hi1, H, L);
                *reinterpret_cast<uint32_t*>(OH + off + 32) = H;
                *reinterpret_cast<uint32_t*>(OL + off + 32) = L;
            }
        }
    }
}

// ---------------------------------------------------------------------------
// O-projection GEMM
// ---------------------------------------------------------------------------
__global__ void __launch_bounds__(256, 2)
gemm3_kernel(const __nv_bfloat16* __restrict__ Ah,
             const __nv_bfloat16* __restrict__ Al,
             const __nv_bfloat16* __restrict__ BhT,
             const __nv_bfloat16* __restrict__ BlT,
             float* __restrict__ C, int ldc)
{
    extern __shared__ char smem[];
    const uint32_t sm0 = smem_u32(smem);
    const int tid  = threadIdx.x;
    const int wid  = tid >> 5;
    const int lane = tid & 31;
    const int wm   = wid & 3;
    const int wn   = wid >> 2;
    const int m0   = blockIdx.y * 128;
    const int n0   = blockIdx.x * 128;

    const int lrow = (lane & 7) + ((lane >> 3) & 1) * 8;
    const int lcol = (lane >> 4) * 8;

    float acc[2][8][4];
    #pragma unroll
    for (int mt = 0; mt < 2; mt++)
        #pragma unroll
        for (int n8 = 0; n8 < 8; n8++)
            #pragma unroll
            for (int j = 0; j < 4; j++) acc[mt][n8][j] = 0.f;

    gemm_mainloop(Ah, Al, BhT, BlT, m0, n0, sm0, tid, wm, wn, lrow, lcol, acc);

    const int cr = lane >> 2;
    const int cc = (lane & 3) * 2;
    #pragma unroll
    for (int mt = 0; mt < 2; mt++) {
        #pragma unroll
        for (int n8 = 0; n8 < 8; n8++) {
            float* base = C + (size_t)(m0 + wm * 32 + mt * 16 + cr) * ldc
                            + n0 + wn * 64 + n8 * 8 + cc;
            *reinterpret_cast<float2*>(base) =
                make_float2(acc[mt][n8][0], acc[mt][n8][1]);
            *reinterpret_cast<float2*>(base + 8 * (size_t)ldc) =
                make_float2(acc[mt][n8][2], acc[mt][n8][3]);
        }
    }
}

// ---------------------------------------------------------------------------
// x split (element-wise)
// ---------------------------------------------------------------------------
__global__ void split_kernel(const float* __restrict__ in,
                             __nv_bfloat16* __restrict__ hi,
                             __nv_bfloat16* __restrict__ lo)
{
    int i = (blockIdx.x * 256 + threadIdx.x) * 4;
    float4 v = *reinterpret_cast<const float4*>(in + i);
    float vv[4] = { v.x, v.y, v.z, v.w };
    __nv_bfloat16 h[4], l[4];
    #pragma unroll
    for (int j = 0; j < 4; j++) {
        h[j] = __float2bfloat16(vv[j]);
        l[j] = __float2bfloat16(vv[j] - __bfloat162float(h[j]));
    }
    *reinterpret_cast<uint2*>(hi + i) = *reinterpret_cast<uint2*>(h);
    *reinterpret_cast<uint2*>(lo + i) = *reinterpret_cast<uint2*>(l);
}

// ---------------------------------------------------------------------------
// All weight transpose-splits in ONE launch (region-decoded grid)
//   regions: wq 4096 blocks, wk 1024, wv 1024, wo 4096 (each 32x32 tile)
// ---------------------------------------------------------------------------
__global__ void wsplit_all_kernel(
    const float* __restrict__ wq, const float* __restrict__ wk,
    const float* __restrict__ wv, const float* __restrict__ wo,
    __nv_bfloat16* __restrict__ wqh, __nv_bfloat16* __restrict__ wql,
    __nv_bfloat16* __restrict__ wkh, __nv_bfloat16* __restrict__ wkl,
    __nv_bfloat16* __restrict__ wvh, __nv_bfloat16* __restrict__ wvl,
    __nv_bfloat16* __restrict__ woh, __nv_bfloat16* __restrict__ wol)
{
    __shared__ float t[32][33];
    int bid = blockIdx.x;
    const float* w;
    __nv_bfloat16 *hiT, *loT;
    int N, local;
    if (bid < 4096)      { w = wq; hiT = wqh; loT = wql; N = DIM;   local = bid; }
    else if (bid < 5120) { w = wk; hiT = wkh; loT = wkl; N = KVDIM; local = bid - 4096; }
    else if (bid < 6144) { w = wv; hiT = wvh; loT = wvl; N = KVDIM; local = bid - 5120; }
    else                 { w = wo; hiT = woh; loT = wol; N = DIM;   local = bid - 6144; }
    const int nbx = N / 32;
    const int n0 = (local % nbx) * 32;
    const int k0 = (local / nbx) * 32;
    const int tx = threadIdx.x, ty = threadIdx.y;
    #pragma unroll
    for (int r = 0; r < 4; r++)
        t[ty + 8 * r][tx] = w[(size_t)(k0 + ty + 8 * r) * N + n0 + tx];
    __syncthreads();
    #pragma unroll
    for (int r = 0; r < 4; r++) {
        int row = ty + 8 * r;
        float v = t[tx][row];
        __nv_bfloat16 h = __float2bfloat16(v);
        __nv_bfloat16 l = __float2bfloat16(v - __bfloat162float(h));
        size_t o = (size_t)(n0 + row) * GK + k0 + tx;
        hiT[o] = h;
        loT[o] = l;
    }
}

// ---------------------------------------------------------------------------
// V transpose-split
// ---------------------------------------------------------------------------
__global__ void vtsplit_kernel(const float* __restrict__ V,
                               __nv_bfloat16* __restrict__ Vth,
                               __nv_bfloat16* __restrict__ Vtl)
{
    __shared__ float t[32][33];
    const int sB = blockIdx.x * 32;
    const int dB = blockIdx.y * 32;
    const int tx = threadIdx.x, ty = threadIdx.y;
    #pragma unroll
    for (int r = 0; r < 4; r++)
        t[ty + 8 * r][tx] = V[(size_t)(sB + ty + 8 * r) * KVDIM + dB + tx];
    __syncthreads();
    #pragma unroll
    for (int r = 0; r < 4; r++) {
        int dd = ty + 8 * r;
        float v = t[tx][dd];
        __nv_bfloat16 h = __float2bfloat16(v);
        __nv_bfloat16 l = __float2bfloat16(v - __bfloat162float(h));
        size_t o = (size_t)(dB + dd) * SEQ + sB + tx;
        Vth[o] = h;
        Vtl[o] = l;
    }
}

// ---------------------------------------------------------------------------
// HMMA flash attention — 2 heads (same KV group) per CTA, 256 threads.
//   warps 0-3: head 2*by, warps 4-7: head 2*by+1; shared KV smem pipeline.
// ---------------------------------------------------------------------------
#define BQ     64
#define BK     64
#define PADH   72
#define ROWB   (PADH * 2)          // 144
#define ATILE  (64 * ROWB)         // 9216
#define ASTAGE (4 * ATILE)         // 36864
#define SM_KV  (4 * ATILE)         // after 4 Q buffers (QH0,QL0,QH1,QL1)
#define ATT_SMEM (SM_KV + 2 * ASTAGE)   // 110592

__device__ __forceinline__ void att_issue(
    uint32_t sb,
    const __nv_bfloat16* __restrict__ Kh, const __nv_bfloat16* __restrict__ Kl,
    const __nv_bfloat16* __restrict__ Vth, const __nv_bfloat16* __restrict__ Vtl,
    int k0, int kh, int tid)
{
    const size_t kbase  = (size_t)kh * HDIM;
    const size_t vtbase = (size_t)kh * HDIM * SEQ;
    const __nv_bfloat16* gp[4] = { Kh, Kl, Vth, Vtl };
    #pragma unroll
    for (int p = 0; p < 4; p++) {
        #pragma unroll
        for (int i = 0; i < 2; i++) {
            int idx = tid + i * 256;           // 0..511
            int r = idx >> 3, q = idx & 7;
            uint32_t so = (uint32_t)(r * ROWB + q * 16);
            const __nv_bfloat16* src = (p < 2)
                ? gp[p] + (size_t)(k0 + r) * KVDIM + kbase + q * 8
                : gp[p] + vtbase + (size_t)r * SEQ + k0 + q * 8;
            CP_ASYNC16(sb + p * ATILE + so, src);
        }
    }
}

__global__ void __launch_bounds__(256, 1)
attn_mma_kernel(const __nv_bfloat16* __restrict__ Qh,
                const __nv_bfloat16* __restrict__ Ql,
                const __nv_bfloat16* __restrict__ Kh,
                const __nv_bfloat16* __restrict__ Kl,
                const __nv_bfloat16* __restrict__ Vth,
                const __nv_bfloat16* __restrict__ Vtl,
                __nv_bfloat16* __restrict__ Ohi,
                __nv_bfloat16* __restrict__ Olo)
{
    extern __shared__ char smem[];
    const uint32_t s0 = smem_u32(smem);
    const int tid = threadIdx.x, wid = tid >> 5, lane = tid & 31;
    const int hd = wid >> 2;                  // 0/1: which head of the pair
    const int w  = wid & 3;                   // q-row sub-tile
    const int h  = blockIdx.y * 2 + hd;
    const int kh = blockIdx.y >> 1;           // shared KV head
    const int q0 = blockIdx.x * BQ;
    const int lrow = (lane & 7) + ((lane >> 3) & 1) * 8;
    const int lcol = (lane >> 4) * 8;
    const int gr = lane >> 2, tg = lane & 3;
    const int NT = SEQ / BK;

    // prologue: 4 Q buffers (QH0,QL0,QH1,QL1) + KV tile 0
    #pragma unroll
    for (int b = 0; b < 4; b++) {
        const __nv_bfloat16* src = (b & 1) ? Ql : Qh;
        const int hh = blockIdx.y * 2 + (b >> 1);
        #pragma unroll
        for (int i = 0; i < 2; i++) {
            int idx = tid + i * 256;
            int r = idx >> 3, q = idx & 7;
            CP_ASYNC16(s0 + b * ATILE + (uint32_t)(r * ROWB + q * 16),
                       src + (size_t)(q0 + r) * DIM + hh * HDIM + q * 8);
        }
    }
    att_issue(s0 + SM_KV, Kh, Kl, Vth, Vtl, 0, kh, tid);
    CP_COMMIT();
    CP_WAIT0();
    __syncthreads();

    // resident Q fragments for this warp's head
    uint32_t qfh[4][4], qfl[4][4];
    {
        const uint32_t qb = s0 + (hd * 2) * ATILE;
        #pragma unroll
        for (int kc = 0; kc < 4; kc++) {
            uint32_t off = (uint32_t)((w * 16 + lrow) * ROWB + (kc * 16 + lcol) * 2);
            ldsm_x4(qfh[kc], qb + off);
            ldsm_x4(qfl[kc], qb + ATILE + off);
        }
    }

    float acc[8][4];
    #pragma unroll
    for (int j = 0; j < 8; j++)
        #pragma unroll
        for (int i = 0; i < 4; i++) acc[j][i] = 0.f;
    float m0 = -1e30f, m1 = -1e30f, l0 = 0.f, l1 = 0.f;

    for (int c = 0; c < NT; c++) {
        if (c + 1 < NT) {
            att_issue(s0 + SM_KV + ((c + 1) & 1) * ASTAGE,
                      Kh, Kl, Vth, Vtl, (c + 1) * BK, kh, tid);
            CP_COMMIT();
            CP_WAIT1();
        } else {
            CP_WAIT0();
        }
        __syncthreads();

        const uint32_t sb  = s0 + SM_KV + (c & 1) * ASTAGE;
        const uint32_t sKh = sb + 0 * ATILE;
        const uint32_t sKl = sb + 1 * ATILE;
        const uint32_t sVh = sb + 2 * ATILE;
        const uint32_t sVl = sb + 3 * ATILE;

        float s[8][4];
        #pragma unroll
        for (int j = 0; j < 8; j++)
            #pragma unroll
            for (int i = 0; i < 4; i++) s[j][i] = 0.f;

        #pragma unroll
        for (int kc = 0; kc < 4; kc++) {
            #pragma unroll
            for (int nt = 0; nt < 4; nt++) {
                uint32_t off = (uint32_t)((nt * 16 + lrow) * ROWB + (kc * 16 + lcol) * 2);
                uint32_t th[4], tl[4];
                ldsm_x4(th, sKh + off);
                ldsm_x4(tl, sKl + off);
                uint32_t b0h[2] = { th[0], th[2] }, b1h[2] = { th[1], th[3] };
                uint32_t b0l[2] = { tl[0], tl[2] }, b1l[2] = { tl[1], tl[3] };
                mma16816(s[2 * nt],     qfh[kc], b0h);
                mma16816(s[2 * nt],     qfh[kc], b0l);
                mma16816(s[2 * nt],     qfl[kc], b0h);
                mma16816(s[2 * nt + 1], qfh[kc], b1h);
                mma16816(s[2 * nt + 1], qfh[kc], b1l);
                mma16816(s[2 * nt + 1], qfl[kc], b1h);
            }
        }

        float tm0 = -1e30f, tm1 = -1e30f;
        #pragma unroll
        for (int j = 0; j < 8; j++) {
            tm0 = fmaxf(tm0, fmaxf(s[j][0], s[j][1]));
            tm1 = fmaxf(tm1, fmaxf(s[j][2], s[j][3]));
        }
        tm0 = fmaxf(tm0, __shfl_xor_sync(0xffffffffu, tm0, 1));
        tm0 = fmaxf(tm0, __shfl_xor_sync(0xffffffffu, tm0, 2));
        tm1 = fmaxf(tm1, __shfl_xor_sync(0xffffffffu, tm1, 1));
        tm1 = fmaxf(tm1, __shfl_xor_sync(0xffffffffu, tm1, 2));

        float nm0 = fmaxf(m0, tm0), nm1 = fmaxf(m1, tm1);
        float corr0 = __expf(m0 - nm0), corr1 = __expf(m1 - nm1);
        m0 = nm0; m1 = nm1;

        float sum0 = 0.f, sum1 = 0.f;
        #pragma unroll
        for (int j = 0; j < 8; j++) {
            s[j][0] = __expf(s[j][0] - m0);
            s[j][1] = __expf(s[j][1] - m0);
            s[j][2] = __expf(s[j][2] - m1);
            s[j][3] = __expf(s[j][3] - m1);
            sum0 += s[j][0] + s[j][1];
            sum1 += s[j][2] + s[j][3];
        }
        sum0 += __shfl_xor_sync(0xffffffffu, sum0, 1);
        sum0 += __shfl_xor_sync(0xffffffffu, sum0, 2);
        sum1 += __shfl_xor_sync(0xffffffffu, sum1, 1);
        sum1 += __shfl_xor_sync(0xffffffffu, sum1, 2);
        l0 = l0 * corr0 + sum0;
        l1 = l1 * corr1 + sum1;

        #pragma unroll
        for (int j = 0; j < 8; j++) {
            acc[j][0] *= corr0; acc[j][1] *= corr0;
            acc[j][2] *= corr1; acc[j][3] *= corr1;
        }

        #pragma unroll
        for (int kc = 0; kc < 4; kc++) {
            uint32_t aph[4], apl[4];
            split2(s[2 * kc][0],     s[2 * kc][1],     aph[0], apl[0]);
            split2(s[2 * kc][2],     s[2 * kc][3],     aph[1], apl[1]);
            split2(s[2 * kc + 1][0], s[2 * kc + 1][1], aph[2], apl[2]);
            split2(s[2 * kc + 1][2], s[2 * kc + 1][3], aph[3], apl[3]);
            #pragma unroll
            for (int nt = 0; nt < 4; nt++) {
                uint32_t off = (uint32_t)((nt * 16 + lrow) * ROWB + (kc * 16 + lcol) * 2);
                uint32_t th[4], tl[4];
                ldsm_x4(th, sVh + off);
                ldsm_x4(tl, sVl + off);
                uint32_t b0h[2] = { th[0], th[2] }, b1h[2] = { th[1], th[3] };
                uint32_t b0l[2] = { tl[0], tl[2] }, b1l[2] = { tl[1], tl[3] };
                mma16816(acc[2 * nt],     aph, b0h);
                mma16816(acc[2 * nt],     aph, b0l);
                mma16816(acc[2 * nt],     apl, b0h);
                mma16816(acc[2 * nt + 1], aph, b1h);
                mma16816(acc[2 * nt + 1], aph, b1l);
                mma16816(acc[2 * nt + 1], apl, b1h);
            }
        }
        __syncthreads();
    }

    const float inv0 = 1.f / l0, inv1 = 1.f / l1;
    #pragma unroll
    for (int j = 0; j < 8; j++) {
        const size_t off0 = (size_t)(q0 + w * 16 + gr) * DIM + h * HDIM + j * 8 + tg * 2;
        const size_t off1 = off0 + 8 * (size_t)DIM;
        uint32_t H, L;
        split2(acc[j][0] * inv0, acc[j][1] * inv0, H, L);
        *reinterpret_cast<uint32_t*>(Ohi + off0) = H;
        *reinterpret_cast<uint32_t*>(Olo + off0) = L;
        split2(acc[j][2] * inv1, acc[j][3] * inv1, H, L);
        *reinterpret_cast<uint32_t*>(Ohi + off1) = H;
        *reinterpret_cast<uint32_t*>(Olo + off1) = L;
    }
}

// ---------------------------------------------------------------------------
// Launch
// ---------------------------------------------------------------------------
extern "C" void kernel_launch(void* const* d_in, const int* in_sizes, int n_in,
                              void* d_out, int out_size)
{
    const float* x  = (const float*)d_in[0];
    const float* wq = (const float*)d_in[1];
    const float* wk = (const float*)d_in[2];
    const float* wv = (const float*)d_in[3];
    const float* wo = (const float*)d_in[4];
    float* out = (float*)d_out;

    float* Vb;
    cudaGetSymbolAddress((void**)&Vb, g_V);

    __nv_bfloat16 *xh, *xl, *Oh, *Ol;
    __nv_bfloat16 *wqh, *wql, *wkh, *wkl, *wvh, *wvl, *woh, *wol;
    __nv_bfloat16 *qsh, *qsl, *ksh, *ksl, *vth, *vtl;
    cudaGetSymbolAddress((void**)&xh, g_xh);
    cudaGetSymbolAddress((void**)&xl, g_xl);
    cudaGetSymbolAddress((void**)&Oh, g_Oh);
    cudaGetSymbolAddress((void**)&Ol, g_Ol);
    cudaGetSymbolAddress((void**)&wqh, g_wqhT);
    cudaGetSymbolAddress((void**)&wql, g_wqlT);
    cudaGetSymbolAddress((void**)&wkh, g_wkhT);
    cudaGetSymbolAddress((void**)&wkl, g_wklT);
    cudaGetSymbolAddress((void**)&wvh, g_wvhT);
    cudaGetSymbolAddress((void**)&wvl, g_wvlT);
    cudaGetSymbolAddress((void**)&woh, g_wohT);
    cudaGetSymbolAddress((void**)&wol, g_wolT);
    cudaGetSymbolAddress((void**)&qsh, g_Qh);
    cudaGetSymbolAddress((void**)&qsl, g_Ql);
    cudaGetSymbolAddress((void**)&ksh, g_Kh);
    cudaGetSymbolAddress((void**)&ksl, g_Kl);
    cudaGetSymbolAddress((void**)&vth, g_Vth);
    cudaGetSymbolAddress((void**)&vtl, g_Vtl);

    cudaFuncSetAttribute(qkv_gemm_kernel,
        cudaFuncAttributeMaxDynamicSharedMemorySize, GEMM_SMEM);
    cudaFuncSetAttribute(gemm3_kernel,
        cudaFuncAttributeMaxDynamicSharedMemorySize, GEMM_SMEM);
    cudaFuncSetAttribute(attn_mma_kernel,
        cudaFuncAttributeMaxDynamicSharedMemorySize, ATT_SMEM);

    // splits
    split_kernel<<<SEQ * DIM / 1024, 256>>>(x, xh, xl);
    wsplit_all_kernel<<<10240, dim3(32, 8)>>>(
        wq, wk, wv, wo, wqh, wql, wkh, wkl, wvh, wvl, woh, wol);

    // fused QKV projection
    qkv_gemm_kernel<<<dim3(24, 16), 256, GEMM_SMEM>>>(
        xh, xl, wqh, wql, wkh, wkl, wvh, wvl,
        qsh, qsl, ksh, ksl, Vb);

    // V transpose-split
    vtsplit_kernel<<<dim3(SEQ / 32, KVDIM / 32), dim3(32, 8)>>>(Vb, vth, vtl);

    // HMMA flash attention (2 heads / CTA)
    attn_mma_kernel<<<dim3(SEQ / BQ, NKV * 2), 256, ATT_SMEM>>>(
        qsh, qsl, ksh, ksl, vth, vtl, Oh, Ol);

    // output projection
    gemm3_kernel<<<dim3(DIM / 128, SEQ / 128), 256, GEMM_SMEM>>>(
        Oh, Ol, woh, wol, out, DIM);
}